// round 2
// baseline (speedup 1.0000x reference)
#include <cuda_runtime.h>
#include <math.h>

// ---------------- problem constants ----------------
#define BB    2
#define CC    512
#define TT    16
#define HH    32
#define WW    32
#define SS    (BB*HH*WW)       // 2048
#define MM    (SS*TT)          // 32768
#define HEADS 8
#define DH    64
#define FF    1365             // inner_ff
#define FF2   2730
#define FHALF 683
#define KPAD  1368             // FF padded to multiple of 8

// ---------------- scratch arena (lifetime-aliased) ----------------
// A = MM*CC floats.  Layout (in units of A):
//   [0,1) xt   [1,2) xn -> later res1   [2,5) q(1)+kv(2) -> later glu(2.67)
//   [5,6) o
#define AUNIT (MM*CC)                       // 16,777,216 floats
__device__ float g_arena[6*(size_t)AUNIT];  // ~402 MB
#define OFF_XT   ((size_t)0)
#define OFF_XN   ((size_t)AUNIT)
#define OFF_RES1 ((size_t)AUNIT)            // aliases xn (dead after kv gemm)
#define OFF_Q    ((size_t)2*AUNIT)
#define OFF_KV   ((size_t)3*AUNIT)
#define OFF_GLU  ((size_t)2*AUNIT)          // aliases q+kv (dead after attn)
#define OFF_O    ((size_t)5*AUNIT)

__device__ float  g_bias[HEADS*TT*TT];      // (8,16,16)
__device__ float  g_wout[KPAD*CC];          // chan_g-folded Wout, zero-padded K
__device__ float2 g_stats[MM];              // per-row (mean, rstd) for channel LN

// ---------------- relative position bias MLP ----------------
__global__ void __launch_bounds__(256) bias_kernel(
    const float* __restrict__ w1, const float* __restrict__ b1,
    const float* __restrict__ w2, const float* __restrict__ b2,
    const float* __restrict__ w3, const float* __restrict__ b3)
{
    __shared__ float h1[256];
    __shared__ float h2[256];
    int i = blockIdx.x >> 4, j = blockIdx.x & 15;
    int tid = threadIdx.x;
    float r   = (float)(i - j);
    float sgn = (r > 0.f) ? 1.f : ((r < 0.f) ? -1.f : 0.f);
    float rel = sgn * logf(fabsf(r) + 1.f);
    float a = rel * w1[tid] + b1[tid];
    h1[tid] = a / (1.f + expf(-a));             // silu
    __syncthreads();
    float acc = b2[tid];
    for (int k = 0; k < 256; k++) acc += h1[k] * w2[k*256 + tid];
    h2[tid] = acc / (1.f + expf(-acc));
    __syncthreads();
    if (tid < 8) {
        float o = b3[tid];
        for (int k = 0; k < 256; k++) o += h2[k] * w3[k*8 + tid];
        g_bias[tid*256 + blockIdx.x] = o;       // [h][i*16+j]
    }
}

// ---------------- fold chan_g into Wout, pad K ----------------
__global__ void woutg_kernel(const float* __restrict__ Wout,
                             const float* __restrict__ chang)
{
    int idx = blockIdx.x*256 + threadIdx.x;
    if (idx >= KPAD*CC) return;
    int k = idx >> 9, n = idx & 511;
    g_wout[idx] = (k < FF) ? chang[k] * Wout[k*CC + n] : 0.f;
}

// ---------------- transpose + embed + LayerNorm over t ----------------
// block: (ctile=16, h, b); tile = 16c x 16t x 32w in smem
__global__ void __launch_bounds__(256) embed_norm_kernel(
    const float* __restrict__ x, const int* __restrict__ fr_p,
    const float* __restrict__ gnorm, const float* __restrict__ pos_emb,
    const float* __restrict__ fr_emb)
{
    float* xt = g_arena + OFF_XT;
    float* xn = g_arena + OFF_XN;
    __shared__ float sx[16*513 + 32];
    __shared__ float pes[256];          // [t][c_local]
    int c0 = blockIdx.x * 16;
    int h  = blockIdx.y;
    int b  = blockIdx.z;
    int tid = threadIdx.x;
    int fr = fr_p[0];
    {
        int t = tid >> 4, c = tid & 15;
        pes[tid] = pos_emb[t*CC + c0 + c] + fr_emb[(fr-1)*CC + c0 + c];
    }
    __syncthreads();
    #pragma unroll
    for (int it = 0; it < 32; it++) {
        int idx = tid + it*256;            // c*512 + t*32 + w  (w fastest)
        int c = idx >> 9;
        int rr = idx & 511;
        int t = rr >> 5;
        int w = rr & 31;
        float xv = x[((size_t)((b*CC + c0 + c)*TT + t))*(HH*WW) + h*WW + w];
        sx[c*513 + t*32 + w] = xv + pes[t*16 + c];
    }
    __syncthreads();
    #pragma unroll
    for (int p = 0; p < 2; p++) {
        int pidx = tid + p*256;
        int c = pidx & 15;
        int w = pidx >> 4;
        int s = (b*HH + h)*WW + w;
        float sum = 0.f, ssq = 0.f;
        #pragma unroll
        for (int t = 0; t < 16; t++) {
            float v = sx[c*513 + t*32 + w];
            sum += v; ssq += v*v;
        }
        float mean = sum * (1.f/16.f);
        float var  = ssq * (1.f/16.f) - mean*mean;
        float rs   = rsqrtf(fmaxf(var, 1e-5f));
        float g    = gnorm[c0 + c];
        #pragma unroll
        for (int t = 0; t < 16; t++) {
            float v = sx[c*513 + t*32 + w];
            size_t addr = (size_t)(s*TT + t)*CC + c0 + c;
            xn[addr] = (v - mean) * rs * g;
            xt[addr] = v - pes[t*16 + c];       // raw x (no embeddings)
        }
    }
}

// ---------------- generic fp32 SGEMM 128x128x8, 8x8 microtile ----------------
// A/C/res addressed as arena offsets; B is a harness input pointer.
__global__ void __launch_bounds__(256) sgemm128_kernel(
    int N, int K, size_t aOff, const float* __restrict__ B,
    long long resOff, size_t cOff)
{
    const float* A   = g_arena + aOff;
    const float* res = (resOff >= 0) ? (g_arena + (size_t)resOff) : (const float*)0;
    float* C = g_arena + cOff;

    __shared__ float As[8*128];
    __shared__ float Bs[8*128];
    int bm = blockIdx.y * 128;
    int bn = blockIdx.x * 128;
    int tid = threadIdx.x;
    int tr = tid >> 4, tc = tid & 15;
    int aRow = tid >> 1, aCol = (tid & 1) * 4;
    int bRow = tid >> 5, bCol = (tid & 31) * 4;
    const float* Ap = A + (size_t)(bm + aRow)*K + aCol;
    const float* Bp = B + (size_t)bRow*N + bn + bCol;

    float acc[8][8] = {};
    for (int k0 = 0; k0 < K; k0 += 8) {
        float4 a4 = *(const float4*)(Ap + k0);
        As[(aCol+0)*128 + aRow] = a4.x;
        As[(aCol+1)*128 + aRow] = a4.y;
        As[(aCol+2)*128 + aRow] = a4.z;
        As[(aCol+3)*128 + aRow] = a4.w;
        *(float4*)&Bs[bRow*128 + bCol] = *(const float4*)(Bp + (size_t)k0*N);
        __syncthreads();
        #pragma unroll
        for (int k = 0; k < 8; k++) {
            float rm[8], rn[8];
            *(float4*)(rm)   = *(float4*)&As[k*128 + tr*8];
            *(float4*)(rm+4) = *(float4*)&As[k*128 + tr*8 + 4];
            *(float4*)(rn)   = *(float4*)&Bs[k*128 + tc*8];
            *(float4*)(rn+4) = *(float4*)&Bs[k*128 + tc*8 + 4];
            #pragma unroll
            for (int i = 0; i < 8; i++)
                #pragma unroll
                for (int j = 0; j < 8; j++)
                    acc[i][j] += rm[i] * rn[j];
        }
        __syncthreads();
    }
    #pragma unroll
    for (int i = 0; i < 8; i++) {
        int m = bm + tr*8 + i;
        size_t off = (size_t)m*N + bn + tc*8;
        #pragma unroll
        for (int j0 = 0; j0 < 8; j0 += 4) {
            float4 v = make_float4(acc[i][j0], acc[i][j0+1], acc[i][j0+2], acc[i][j0+3]);
            if (res) {
                float4 rr = *(const float4*)(res + off + j0);
                v.x += rr.x; v.y += rr.y; v.z += rr.z; v.w += rr.w;
            }
            *(float4*)(C + off + j0) = v;
        }
    }
}

// ---------------- attention: one block per (s, head) ----------------
__global__ void __launch_bounds__(128) attn_kernel()
{
    const float* q  = g_arena + OFF_Q;
    const float* kv = g_arena + OFF_KV;
    float*       o  = g_arena + OFF_O;
    __shared__ float qs[16*65], ks[16*65], vs[16*65], sm[16*17];
    int s  = blockIdx.x >> 3;
    int hd = blockIdx.x & 7;
    int tid = threadIdx.x;
    for (int idx = tid; idx < 1024; idx += 128) {
        int t = idx >> 6, d = idx & 63;
        size_t base = (size_t)(s*16 + t);
        qs[t*65 + d] = q [base*512  + hd*64 + d];
        ks[t*65 + d] = kv[base*1024 + hd*64 + d];
        vs[t*65 + d] = kv[base*1024 + 512 + hd*64 + d];
    }
    __syncthreads();
    for (int e = tid; e < 256; e += 128) {
        int i = e >> 4, j = e & 15;
        float acc = 0.f;
        #pragma unroll
        for (int d = 0; d < 64; d++) acc += qs[i*65 + d] * ks[j*65 + d];
        sm[i*17 + j] = acc * 0.125f + g_bias[hd*256 + i*16 + j];
    }
    __syncthreads();
    if (tid < 16) {
        int i = tid;
        float mx = -1e30f;
        for (int j = 0; j < 16; j++) mx = fmaxf(mx, sm[i*17 + j]);
        float ssum = 0.f;
        for (int j = 0; j < 16; j++) { float e2 = expf(sm[i*17+j] - mx); sm[i*17+j] = e2; ssum += e2; }
        float inv = 1.f / ssum;
        for (int j = 0; j < 16; j++) sm[i*17 + j] *= inv;
    }
    __syncthreads();
    for (int e = tid; e < 1024; e += 128) {
        int i = e >> 6, d = e & 63;
        float acc = 0.f;
        #pragma unroll
        for (int j = 0; j < 16; j++) acc += sm[i*17 + j] * vs[j*65 + d];
        o[(size_t)(s*16 + i)*512 + hd*64 + d] = acc;
    }
}

// ---------------- Win GEMM fused with GeGLU: 128x64 tile ----------------
__global__ void __launch_bounds__(256) gemm_glu_kernel(const float* __restrict__ Win)
{
    const float* res1 = g_arena + OFF_RES1;
    float*       glu  = g_arena + OFF_GLU;
    __shared__ float As [8*128];
    __shared__ float Bs1[8*64];
    __shared__ float Bs2[8*64];
    int bm = blockIdx.y * 128;
    int bn = blockIdx.x * 64;
    int tid = threadIdx.x;
    int tr = tid >> 4, tc = tid & 15;          // 16x16 threads, 8x4 microtile
    int aRow = tid >> 1, aCol = (tid & 1) * 4;
    const float* Ap = res1 + (size_t)(bm + aRow)*512 + aCol;

    float a1[8][4] = {}, a2[8][4] = {};
    for (int k0 = 0; k0 < 512; k0 += 8) {
        float4 a4 = *(const float4*)(Ap + k0);
        As[(aCol+0)*128 + aRow] = a4.x;
        As[(aCol+1)*128 + aRow] = a4.y;
        As[(aCol+2)*128 + aRow] = a4.z;
        As[(aCol+3)*128 + aRow] = a4.w;
        #pragma unroll
        for (int l = tid; l < 512; l += 256) {
            int r = l >> 6, cc = l & 63;
            int col = bn + cc;
            float v1 = 0.f, v2 = 0.f;
            if (col < FF) {
                size_t base = (size_t)(k0 + r)*FF2 + col;
                v1 = Win[base];
                v2 = Win[base + FF];
            }
            Bs1[l] = v1; Bs2[l] = v2;
        }
        __syncthreads();
        #pragma unroll
        for (int k = 0; k < 8; k++) {
            float rm[8], rn1[4], rn2[4];
            *(float4*)(rm)   = *(float4*)&As[k*128 + tr*8];
            *(float4*)(rm+4) = *(float4*)&As[k*128 + tr*8 + 4];
            *(float4*)(rn1)  = *(float4*)&Bs1[k*64 + tc*4];
            *(float4*)(rn2)  = *(float4*)&Bs2[k*64 + tc*4];
            #pragma unroll
            for (int i = 0; i < 8; i++)
                #pragma unroll
                for (int j = 0; j < 4; j++) {
                    a1[i][j] += rm[i] * rn1[j];
                    a2[i][j] += rm[i] * rn2[j];
                }
        }
        __syncthreads();
    }
    #pragma unroll
    for (int i = 0; i < 8; i++) {
        int m = bm + tr*8 + i;
        #pragma unroll
        for (int j = 0; j < 4; j++) {
            int col = bn + tc*4 + j;
            if (col < FF) {
                float gte = a2[i][j];
                float gl  = 0.5f * gte * (1.f + erff(gte * 0.70710678118654752f));
                glu[(size_t)m*FF + col] = a1[i][j] * gl;
            }
        }
    }
}

// ---------------- time-shift + channel LN: stats only ----------------
__device__ __forceinline__ float shifted_val(const float* glu, int m, int t, int f)
{
    if (f < FHALF) return glu[(size_t)m*FF + f];
    return (t > 0) ? glu[(size_t)(m-1)*FF + f] : 0.f;
}

__global__ void __launch_bounds__(128) stats_kernel()
{
    const float* glu = g_arena + OFF_GLU;
    int m = blockIdx.x;
    int t = m & 15;
    int tid = threadIdx.x;
    float s = 0.f, ss = 0.f;
    for (int f = tid; f < FF; f += 128) {
        float v = shifted_val(glu, m, t, f);
        s += v; ss += v*v;
    }
    #pragma unroll
    for (int o = 16; o; o >>= 1) {
        s  += __shfl_down_sync(0xffffffffu, s, o);
        ss += __shfl_down_sync(0xffffffffu, ss, o);
    }
    __shared__ float rA[4], rB[4];
    int wid = tid >> 5, lane = tid & 31;
    if (lane == 0) { rA[wid] = s; rB[wid] = ss; }
    __syncthreads();
    if (tid == 0) {
        float S = 0.f, SQ = 0.f;
        for (int i = 0; i < 4; i++) { S += rA[i]; SQ += rB[i]; }
        float mean = S * (1.f/FF);
        float var  = SQ * (1.f/FF) - mean*mean;
        g_stats[m] = make_float2(mean, rsqrtf(fmaxf(var, 1e-5f)));
    }
}

// ---------------- final GEMM (K=1368) with fused shift+norm A-load ----------------
// out[b][n][t][h][w] = sum_k norm(shifted(glu))[m][k] * wout[k][n] + res1[m][n]
__global__ void __launch_bounds__(256) gemm_final_kernel(float* __restrict__ out)
{
    const float* glu  = g_arena + OFF_GLU;
    const float* res1 = g_arena + OFF_RES1;
    const int N = CC, K = KPAD;
    __shared__ float As[8*128];
    __shared__ float Bs[8*128];
    int bm = blockIdx.y * 128;
    int bn = blockIdx.x * 128;
    int tid = threadIdx.x;
    int tr = tid >> 4, tc = tid & 15;
    int aRow = tid >> 1, aCol = (tid & 1) * 4;
    int bRow = tid >> 5, bCol = (tid & 31) * 4;
    const float* Bp = g_wout + (size_t)bRow*N + bn + bCol;

    int    am    = bm + aRow;
    int    at    = am & 15;
    float2 st    = g_stats[am];
    float  mean  = st.x, rstd = st.y;
    const float* gRow  = glu + (size_t)am*FF;
    const float* gPrev = glu + (size_t)(am-1)*FF;   // only read when at>0

    float acc[8][8] = {};
    for (int k0 = 0; k0 < K; k0 += 8) {
        #pragma unroll
        for (int i = 0; i < 4; i++) {
            int k = k0 + aCol + i;
            float v = 0.f;
            if (k < FF) {
                float raw;
                if (k < FHALF)      raw = gRow[k];
                else if (at > 0)    raw = gPrev[k];
                else                raw = 0.f;
                v = (raw - mean) * rstd;
            }
            As[(aCol+i)*128 + aRow] = v;
        }
        *(float4*)&Bs[bRow*128 + bCol] = *(const float4*)(Bp + (size_t)k0*N);
        __syncthreads();
        #pragma unroll
        for (int k = 0; k < 8; k++) {
            float rm[8], rn[8];
            *(float4*)(rm)   = *(float4*)&As[k*128 + tr*8];
            *(float4*)(rm+4) = *(float4*)&As[k*128 + tr*8 + 4];
            *(float4*)(rn)   = *(float4*)&Bs[k*128 + tc*8];
            *(float4*)(rn+4) = *(float4*)&Bs[k*128 + tc*8 + 4];
            #pragma unroll
            for (int i = 0; i < 8; i++)
                #pragma unroll
                for (int j = 0; j < 8; j++)
                    acc[i][j] += rm[i] * rn[j];
        }
        __syncthreads();
    }
    // epilogue: scatter to (b, n, t, h, w) + residual
    #pragma unroll
    for (int i = 0; i < 8; i++) {
        int m  = bm + tr*8 + i;
        int sI = m >> 4, t = m & 15;
        int b  = sI >> 10, hw = sI & 1023;
        #pragma unroll
        for (int j = 0; j < 8; j++) {
            int n = bn + tc*8 + j;
            out[((size_t)(b*CC + n)*TT + t)*(HH*WW) + hw] =
                acc[i][j] + res1[(size_t)m*CC + n];
        }
    }
}

// ---------------- launch ----------------
extern "C" void kernel_launch(void* const* d_in, const int* in_sizes, int n_in,
                              void* d_out, int out_size)
{
    (void)in_sizes; (void)n_in; (void)out_size;
    const float* x     = (const float*)d_in[0];
    const int*   fr    = (const int*)  d_in[1];
    const float* gnorm = (const float*)d_in[2];
    const float* Wq    = (const float*)d_in[3];
    const float* Wkv   = (const float*)d_in[4];
    const float* Wo    = (const float*)d_in[5];
    const float* pos   = (const float*)d_in[6];
    const float* fre   = (const float*)d_in[7];
    const float* w1    = (const float*)d_in[8];
    const float* b1    = (const float*)d_in[9];
    const float* w2    = (const float*)d_in[10];
    const float* b2    = (const float*)d_in[11];
    const float* w3    = (const float*)d_in[12];
    const float* b3    = (const float*)d_in[13];
    const float* Win   = (const float*)d_in[14];
    const float* chang = (const float*)d_in[15];
    const float* Wout  = (const float*)d_in[16];
    float* out = (float*)d_out;

    bias_kernel<<<256, 256>>>(w1, b1, w2, b2, w3, b3);
    woutg_kernel<<<(KPAD*CC + 255)/256, 256>>>(Wout, chang);
    embed_norm_kernel<<<dim3(CC/16, HH, BB), 256>>>(x, fr, gnorm, pos, fre);
    // q = xn @ Wq
    sgemm128_kernel<<<dim3(CC/128, MM/128), 256>>>(CC,   CC, OFF_XN, Wq,  -1, OFF_Q);
    // kv = xn @ Wkv
    sgemm128_kernel<<<dim3(2*CC/128, MM/128), 256>>>(2*CC, CC, OFF_XN, Wkv, -1, OFF_KV);
    attn_kernel<<<SS*HEADS, 128>>>();
    // res1 = o @ Wo + xt
    sgemm128_kernel<<<dim3(CC/128, MM/128), 256>>>(CC, CC, OFF_O, Wo,
                                                   (long long)OFF_XT, OFF_RES1);
    // glu = (res1 @ Win)[:FF] * gelu((res1 @ Win)[FF:])
    gemm_glu_kernel<<<dim3((FF + 63)/64, MM/128), 256>>>(Win);
    stats_kernel<<<MM, 128>>>();
    gemm_final_kernel<<<dim3(CC/128, MM/128), 256>>>(out);
}

// round 3
// speedup vs baseline: 1.8695x; 1.8695x over previous
#include <cuda_runtime.h>
#include <math.h>
#include <stdint.h>

// ---------------- problem constants ----------------
#define BB    2
#define CC    512
#define TT    16
#define HH    32
#define WW    32
#define SS    (BB*HH*WW)       // 2048
#define MM    (SS*TT)          // 32768
#define HEADS 8
#define DH    64
#define FF    1365             // inner_ff
#define FF2   2730
#define FHALF 683
#define KP2   1376             // FF padded to multiple of 16

// ---------------- scratch arena (lifetime-aliased) ----------------
#define AUNIT (MM*CC)                       // 16,777,216 floats
__device__ float g_arena[6*(size_t)AUNIT];  // ~402 MB
#define OFF_XT   ((size_t)0)
#define OFF_XN   ((size_t)AUNIT)
#define OFF_RES1 ((size_t)AUNIT)            // aliases xn (dead after kv gemm)
#define OFF_Q    ((size_t)2*AUNIT)
#define OFF_KV   ((size_t)3*AUNIT)
#define OFF_GLU  ((size_t)2*AUNIT)          // aliases q+kv (dead after attn)
#define OFF_O    ((size_t)5*AUNIT)

__device__ float  g_bias[HEADS*TT*TT];      // (8,16,16)
__device__ float  g_wout[KP2*CC];           // chan_g-folded Wout, zero-padded K
__device__ float2 g_stats[MM];              // per-row (mean, rstd) for channel LN

// ---------------- tf32 helpers ----------------
__device__ __forceinline__ uint32_t f2tf(float f) {
    uint32_t u;
    asm("cvt.rna.tf32.f32 %0, %1;" : "=r"(u) : "f"(f));
    return u;
}
__device__ __forceinline__ void mma8(float* d, const uint32_t* a, const uint32_t* b) {
    asm volatile("mma.sync.aligned.m16n8k8.row.col.f32.tf32.tf32.f32 "
        "{%0,%1,%2,%3},{%4,%5,%6,%7},{%8,%9},{%0,%1,%2,%3};"
        : "+f"(d[0]), "+f"(d[1]), "+f"(d[2]), "+f"(d[3])
        : "r"(a[0]), "r"(a[1]), "r"(a[2]), "r"(a[3]), "r"(b[0]), "r"(b[1]));
}

#define ASTR 20     // A smem row stride (conflict-free frag loads)
#define BSTR 136    // B smem row stride (128-wide tiles)
#define BSTR2 72    // B smem row stride (64-wide tiles)

// ---------------- relative position bias MLP ----------------
__global__ void __launch_bounds__(256) bias_kernel(
    const float* __restrict__ w1, const float* __restrict__ b1,
    const float* __restrict__ w2, const float* __restrict__ b2,
    const float* __restrict__ w3, const float* __restrict__ b3)
{
    __shared__ float h1[256];
    __shared__ float h2[256];
    int i = blockIdx.x >> 4, j = blockIdx.x & 15;
    int tid = threadIdx.x;
    float r   = (float)(i - j);
    float sgn = (r > 0.f) ? 1.f : ((r < 0.f) ? -1.f : 0.f);
    float rel = sgn * logf(fabsf(r) + 1.f);
    float a = rel * w1[tid] + b1[tid];
    h1[tid] = a / (1.f + expf(-a));             // silu
    __syncthreads();
    float acc = b2[tid];
    for (int k = 0; k < 256; k++) acc += h1[k] * w2[k*256 + tid];
    h2[tid] = acc / (1.f + expf(-acc));
    __syncthreads();
    if (tid < 8) {
        float o = b3[tid];
        for (int k = 0; k < 256; k++) o += h2[k] * w3[k*8 + tid];
        g_bias[tid*256 + blockIdx.x] = o;       // [h][i*16+j]
    }
}

// ---------------- fold chan_g into Wout, pad K ----------------
__global__ void woutg_kernel(const float* __restrict__ Wout,
                             const float* __restrict__ chang)
{
    int idx = blockIdx.x*256 + threadIdx.x;
    if (idx >= KP2*CC) return;
    int k = idx >> 9, n = idx & 511;
    g_wout[idx] = (k < FF) ? chang[k] * Wout[k*CC + n] : 0.f;
}

// ---------------- transpose + embed + LayerNorm over t ----------------
__global__ void __launch_bounds__(256) embed_norm_kernel(
    const float* __restrict__ x, const int* __restrict__ fr_p,
    const float* __restrict__ gnorm, const float* __restrict__ pos_emb,
    const float* __restrict__ fr_emb)
{
    float* xt = g_arena + OFF_XT;
    float* xn = g_arena + OFF_XN;
    __shared__ float sx[16*513 + 32];
    __shared__ float pes[256];          // [t][c_local]
    int c0 = blockIdx.x * 16;
    int h  = blockIdx.y;
    int b  = blockIdx.z;
    int tid = threadIdx.x;
    int fr = fr_p[0];
    {
        int t = tid >> 4, c = tid & 15;
        pes[tid] = pos_emb[t*CC + c0 + c] + fr_emb[(fr-1)*CC + c0 + c];
    }
    __syncthreads();
    #pragma unroll
    for (int it = 0; it < 32; it++) {
        int idx = tid + it*256;            // c*512 + t*32 + w  (w fastest)
        int c = idx >> 9;
        int rr = idx & 511;
        int t = rr >> 5;
        int w = rr & 31;
        float xv = x[((size_t)((b*CC + c0 + c)*TT + t))*(HH*WW) + h*WW + w];
        sx[c*513 + t*32 + w] = xv + pes[t*16 + c];
    }
    __syncthreads();
    #pragma unroll
    for (int p = 0; p < 2; p++) {
        int pidx = tid + p*256;
        int c = pidx & 15;
        int w = pidx >> 4;
        int s = (b*HH + h)*WW + w;
        float sum = 0.f, ssq = 0.f;
        #pragma unroll
        for (int t = 0; t < 16; t++) {
            float v = sx[c*513 + t*32 + w];
            sum += v; ssq += v*v;
        }
        float mean = sum * (1.f/16.f);
        float var  = ssq * (1.f/16.f) - mean*mean;
        float rs   = rsqrtf(fmaxf(var, 1e-5f));
        float g    = gnorm[c0 + c];
        #pragma unroll
        for (int t = 0; t < 16; t++) {
            float v = sx[c*513 + t*32 + w];
            size_t addr = (size_t)(s*TT + t)*CC + c0 + c;
            xn[addr] = (v - mean) * rs * g;
            xt[addr] = v - pes[t*16 + c];       // raw x (no embeddings)
        }
    }
}

// ---------------- generic TF32 GEMM 128x128x16, warp 32x64 ----------------
__global__ void __launch_bounds__(256) gemm_tf32_kernel(
    int N, int K, size_t aOff, const float* __restrict__ Bg,
    long long resOff, size_t cOff)
{
    const float* A   = g_arena + aOff;
    const float* res = (resOff >= 0) ? (g_arena + (size_t)resOff) : (const float*)0;
    float* C = g_arena + cOff;

    __shared__ uint32_t As[2][128*ASTR];
    __shared__ uint32_t Bs[2][16*BSTR];

    int bm = blockIdx.y * 128;
    int bn = blockIdx.x * 128;
    int tid = threadIdx.x;
    int lane = tid & 31, warp = tid >> 5;
    int wm0 = (warp >> 1) * 32, wn0 = (warp & 1) * 64;
    int grp = lane >> 2, qd = lane & 3;
    int aRow = tid >> 1, aCol = (tid & 1) * 8;
    int bRow = tid >> 5, bCol = (tid & 31) * 4;
    const float* Ap = A + (size_t)(bm + aRow)*K + aCol;
    const float* Bp = Bg + bn + bCol;

    float4 ra0, ra1, rb0, rb1;
    ra0 = *(const float4*)(Ap);
    ra1 = *(const float4*)(Ap + 4);
    rb0 = *(const float4*)(Bp + (size_t)bRow*N);
    rb1 = *(const float4*)(Bp + (size_t)(bRow + 8)*N);

    auto sts = [&](int buf) {
        uint32_t* a = As[buf] + aRow*ASTR + aCol;
        a[0]=f2tf(ra0.x); a[1]=f2tf(ra0.y); a[2]=f2tf(ra0.z); a[3]=f2tf(ra0.w);
        a[4]=f2tf(ra1.x); a[5]=f2tf(ra1.y); a[6]=f2tf(ra1.z); a[7]=f2tf(ra1.w);
        uint32_t* b0 = Bs[buf] + bRow*BSTR + bCol;
        b0[0]=f2tf(rb0.x); b0[1]=f2tf(rb0.y); b0[2]=f2tf(rb0.z); b0[3]=f2tf(rb0.w);
        uint32_t* b1 = Bs[buf] + (bRow + 8)*BSTR + bCol;
        b1[0]=f2tf(rb1.x); b1[1]=f2tf(rb1.y); b1[2]=f2tf(rb1.z); b1[3]=f2tf(rb1.w);
    };
    sts(0);
    __syncthreads();

    float acc[2][8][4] = {};
    int nk = K >> 4;
    for (int i = 0; i < nk; i++) {
        int buf = i & 1;
        if (i + 1 < nk) {
            const float* Ap2 = Ap + (i + 1)*16;
            ra0 = *(const float4*)(Ap2);
            ra1 = *(const float4*)(Ap2 + 4);
            const float* Bp2 = Bp + (size_t)(i + 1)*16*N;
            rb0 = *(const float4*)(Bp2 + (size_t)bRow*N);
            rb1 = *(const float4*)(Bp2 + (size_t)(bRow + 8)*N);
        }
        #pragma unroll
        for (int kc = 0; kc < 16; kc += 8) {
            uint32_t af[2][4];
            #pragma unroll
            for (int mi = 0; mi < 2; mi++) {
                int r = wm0 + mi*16 + grp;
                const uint32_t* as = As[buf];
                af[mi][0] = as[r*ASTR + kc + qd];
                af[mi][1] = as[(r + 8)*ASTR + kc + qd];
                af[mi][2] = as[r*ASTR + kc + qd + 4];
                af[mi][3] = as[(r + 8)*ASTR + kc + qd + 4];
            }
            uint32_t bf[8][2];
            #pragma unroll
            for (int ni = 0; ni < 8; ni++) {
                int c = wn0 + ni*8 + grp;
                const uint32_t* bs = Bs[buf];
                bf[ni][0] = bs[(kc + qd)*BSTR + c];
                bf[ni][1] = bs[(kc + qd + 4)*BSTR + c];
            }
            #pragma unroll
            for (int mi = 0; mi < 2; mi++)
                #pragma unroll
                for (int ni = 0; ni < 8; ni++)
                    mma8(acc[mi][ni], af[mi], bf[ni]);
        }
        if (i + 1 < nk) sts((i + 1) & 1);
        __syncthreads();
    }

    #pragma unroll
    for (int mi = 0; mi < 2; mi++) {
        #pragma unroll
        for (int ni = 0; ni < 8; ni++) {
            int r = bm + wm0 + mi*16 + grp;
            int c = bn + wn0 + ni*8 + 2*qd;
            float* d = acc[mi][ni];
            float2 v0 = make_float2(d[0], d[1]);
            float2 v1 = make_float2(d[2], d[3]);
            if (res) {
                float2 r0 = *(const float2*)(res + (size_t)r*N + c);
                float2 r1 = *(const float2*)(res + (size_t)(r + 8)*N + c);
                v0.x += r0.x; v0.y += r0.y;
                v1.x += r1.x; v1.y += r1.y;
            }
            *(float2*)(C + (size_t)r*N + c)       = v0;
            *(float2*)(C + (size_t)(r + 8)*N + c) = v1;
        }
    }
}

// ---------------- attention: one block per (s, head) ----------------
__global__ void __launch_bounds__(128) attn_kernel()
{
    const float* q  = g_arena + OFF_Q;
    const float* kv = g_arena + OFF_KV;
    float*       o  = g_arena + OFF_O;
    __shared__ float qs[16*65], ks[16*65], vs[16*65], sm[16*17];
    int s  = blockIdx.x >> 3;
    int hd = blockIdx.x & 7;
    int tid = threadIdx.x;
    for (int idx = tid; idx < 1024; idx += 128) {
        int t = idx >> 6, d = idx & 63;
        size_t base = (size_t)(s*16 + t);
        qs[t*65 + d] = q [base*512  + hd*64 + d];
        ks[t*65 + d] = kv[base*1024 + hd*64 + d];
        vs[t*65 + d] = kv[base*1024 + 512 + hd*64 + d];
    }
    __syncthreads();
    for (int e = tid; e < 256; e += 128) {
        int i = e >> 4, j = e & 15;
        float acc = 0.f;
        #pragma unroll
        for (int d = 0; d < 64; d++) acc += qs[i*65 + d] * ks[j*65 + d];
        sm[i*17 + j] = acc * 0.125f + g_bias[hd*256 + i*16 + j];
    }
    __syncthreads();
    if (tid < 16) {
        int i = tid;
        float mx = -1e30f;
        for (int j = 0; j < 16; j++) mx = fmaxf(mx, sm[i*17 + j]);
        float ssum = 0.f;
        for (int j = 0; j < 16; j++) { float e2 = expf(sm[i*17+j] - mx); sm[i*17+j] = e2; ssum += e2; }
        float inv = 1.f / ssum;
        for (int j = 0; j < 16; j++) sm[i*17 + j] *= inv;
    }
    __syncthreads();
    for (int e = tid; e < 1024; e += 128) {
        int i = e >> 6, d = e & 63;
        float acc = 0.f;
        #pragma unroll
        for (int j = 0; j < 16; j++) acc += sm[i*17 + j] * vs[j*65 + d];
        o[(size_t)(s*16 + i)*512 + hd*64 + d] = acc;
    }
}

// ---------------- Win GEMM fused with GeGLU (TF32): 128x64 out tile ----------------
__global__ void __launch_bounds__(256) gemm_glu_tf32_kernel(const float* __restrict__ Win)
{
    const float* A   = g_arena + OFF_RES1;
    float*       glu = g_arena + OFF_GLU;

    __shared__ uint32_t As[2][128*ASTR];
    __shared__ uint32_t B1[2][16*BSTR2];
    __shared__ uint32_t B2[2][16*BSTR2];

    int bm = blockIdx.y * 128;
    int bn = blockIdx.x * 64;
    int tid = threadIdx.x;
    int lane = tid & 31, warp = tid >> 5;
    int wm0 = (warp >> 1) * 32, wn0 = (warp & 1) * 32;
    int grp = lane >> 2, qd = lane & 3;
    int aRow = tid >> 1, aCol = (tid & 1) * 8;
    int bRow = tid >> 4, bCol4 = (tid & 15) * 4;
    const float* Ap = A + (size_t)(bm + aRow)*512 + aCol;

    float4 ra0, ra1;
    float rb1[4], rb2[4];

    auto ldgB = [&](int k0) {
        #pragma unroll
        for (int j = 0; j < 4; j++) {
            int col = bn + bCol4 + j;
            float v1 = 0.f, v2 = 0.f;
            if (col < FF) {
                size_t base = (size_t)(k0 + bRow)*FF2 + col;
                v1 = Win[base];
                v2 = Win[base + FF];
            }
            rb1[j] = v1; rb2[j] = v2;
        }
    };
    auto sts = [&](int buf) {
        uint32_t* a = As[buf] + aRow*ASTR + aCol;
        a[0]=f2tf(ra0.x); a[1]=f2tf(ra0.y); a[2]=f2tf(ra0.z); a[3]=f2tf(ra0.w);
        a[4]=f2tf(ra1.x); a[5]=f2tf(ra1.y); a[6]=f2tf(ra1.z); a[7]=f2tf(ra1.w);
        uint32_t* p1 = B1[buf] + bRow*BSTR2 + bCol4;
        uint32_t* p2 = B2[buf] + bRow*BSTR2 + bCol4;
        #pragma unroll
        for (int j = 0; j < 4; j++) { p1[j] = f2tf(rb1[j]); p2[j] = f2tf(rb2[j]); }
    };

    ra0 = *(const float4*)(Ap);
    ra1 = *(const float4*)(Ap + 4);
    ldgB(0);
    sts(0);
    __syncthreads();

    float a1[2][4][4] = {}, a2[2][4][4] = {};
    const int nk = 512 >> 4;
    for (int i = 0; i < nk; i++) {
        int buf = i & 1;
        if (i + 1 < nk) {
            const float* Ap2 = Ap + (i + 1)*16;
            ra0 = *(const float4*)(Ap2);
            ra1 = *(const float4*)(Ap2 + 4);
            ldgB((i + 1)*16);
        }
        #pragma unroll
        for (int kc = 0; kc < 16; kc += 8) {
            uint32_t af[2][4];
            #pragma unroll
            for (int mi = 0; mi < 2; mi++) {
                int r = wm0 + mi*16 + grp;
                const uint32_t* as = As[buf];
                af[mi][0] = as[r*ASTR + kc + qd];
                af[mi][1] = as[(r + 8)*ASTR + kc + qd];
                af[mi][2] = as[r*ASTR + kc + qd + 4];
                af[mi][3] = as[(r + 8)*ASTR + kc + qd + 4];
            }
            uint32_t bf1[4][2], bf2[4][2];
            #pragma unroll
            for (int ni = 0; ni < 4; ni++) {
                int c = wn0 + ni*8 + grp;
                bf1[ni][0] = B1[buf][(kc + qd)*BSTR2 + c];
                bf1[ni][1] = B1[buf][(kc + qd + 4)*BSTR2 + c];
                bf2[ni][0] = B2[buf][(kc + qd)*BSTR2 + c];
                bf2[ni][1] = B2[buf][(kc + qd + 4)*BSTR2 + c];
            }
            #pragma unroll
            for (int mi = 0; mi < 2; mi++)
                #pragma unroll
                for (int ni = 0; ni < 4; ni++) {
                    mma8(a1[mi][ni], af[mi], bf1[ni]);
                    mma8(a2[mi][ni], af[mi], bf2[ni]);
                }
        }
        if (i + 1 < nk) sts((i + 1) & 1);
        __syncthreads();
    }

    #pragma unroll
    for (int mi = 0; mi < 2; mi++) {
        #pragma unroll
        for (int ni = 0; ni < 4; ni++) {
            int c = bn + wn0 + ni*8 + 2*qd;
            #pragma unroll
            for (int half = 0; half < 2; half++) {
                int r = bm + wm0 + mi*16 + grp + half*8;
                #pragma unroll
                for (int l = 0; l < 2; l++) {
                    int col = c + l;
                    if (col < FF) {
                        float y1 = a1[mi][ni][half*2 + l];
                        float gt = a2[mi][ni][half*2 + l];
                        float gl = 0.5f * gt * (1.f + erff(gt * 0.70710678118654752f));
                        glu[(size_t)r*FF + col] = y1 * gl;
                    }
                }
            }
        }
    }
}

// ---------------- time-shift + channel LN: stats only ----------------
__device__ __forceinline__ float shifted_val(const float* glu, int m, int t, int f)
{
    if (f < FHALF) return glu[(size_t)m*FF + f];
    return (t > 0) ? glu[(size_t)(m-1)*FF + f] : 0.f;
}

__global__ void __launch_bounds__(128) stats_kernel()
{
    const float* glu = g_arena + OFF_GLU;
    int m = blockIdx.x;
    int t = m & 15;
    int tid = threadIdx.x;
    float s = 0.f, ss = 0.f;
    for (int f = tid; f < FF; f += 128) {
        float v = shifted_val(glu, m, t, f);
        s += v; ss += v*v;
    }
    #pragma unroll
    for (int o = 16; o; o >>= 1) {
        s  += __shfl_down_sync(0xffffffffu, s, o);
        ss += __shfl_down_sync(0xffffffffu, ss, o);
    }
    __shared__ float rA[4], rB[4];
    int wid = tid >> 5, lane = tid & 31;
    if (lane == 0) { rA[wid] = s; rB[wid] = ss; }
    __syncthreads();
    if (tid == 0) {
        float S = 0.f, SQ = 0.f;
        for (int i = 0; i < 4; i++) { S += rA[i]; SQ += rB[i]; }
        float mean = S * (1.f/FF);
        float var  = SQ * (1.f/FF) - mean*mean;
        g_stats[m] = make_float2(mean, rsqrtf(fmaxf(var, 1e-5f)));
    }
}

// ---------------- final TF32 GEMM (K=1376) with fused shift+norm A-load ----------------
__global__ void __launch_bounds__(256) gemm_final_tf32_kernel(float* __restrict__ out)
{
    const float* glu  = g_arena + OFF_GLU;
    const float* res1 = g_arena + OFF_RES1;
    const int N = CC, K = KP2;

    __shared__ uint32_t As[2][128*ASTR];
    __shared__ uint32_t Bs[2][16*BSTR];

    int bm = blockIdx.y * 128;
    int bn = blockIdx.x * 128;
    int tid = threadIdx.x;
    int lane = tid & 31, warp = tid >> 5;
    int wm0 = (warp >> 1) * 32, wn0 = (warp & 1) * 64;
    int grp = lane >> 2, qd = lane & 3;
    int aRow = tid >> 1, aCol = (tid & 1) * 8;
    int bRow = tid >> 5, bCol = (tid & 31) * 4;

    int    am   = bm + aRow;
    int    at   = am & 15;
    float2 st   = g_stats[am];
    float  mean = st.x, rstd = st.y;
    const float* gRow  = glu + (size_t)am*FF;
    const float* gPrev = glu + (size_t)(am - 1)*FF;  // only read when at>0
    const float* Bp = g_wout + bn + bCol;

    float ra[8];
    float4 rb0, rb1;

    auto ldgA = [&](int k0) {
        #pragma unroll
        for (int j = 0; j < 8; j++) {
            int k = k0 + aCol + j;
            float v = 0.f;
            if (k < FF) {
                float raw;
                if (k < FHALF)   raw = gRow[k];
                else if (at > 0) raw = gPrev[k];
                else             raw = 0.f;
                v = (raw - mean) * rstd;
            }
            ra[j] = v;
        }
    };
    auto sts = [&](int buf) {
        uint32_t* a = As[buf] + aRow*ASTR + aCol;
        #pragma unroll
        for (int j = 0; j < 8; j++) a[j] = f2tf(ra[j]);
        uint32_t* b0 = Bs[buf] + bRow*BSTR + bCol;
        b0[0]=f2tf(rb0.x); b0[1]=f2tf(rb0.y); b0[2]=f2tf(rb0.z); b0[3]=f2tf(rb0.w);
        uint32_t* b1 = Bs[buf] + (bRow + 8)*BSTR + bCol;
        b1[0]=f2tf(rb1.x); b1[1]=f2tf(rb1.y); b1[2]=f2tf(rb1.z); b1[3]=f2tf(rb1.w);
    };

    ldgA(0);
    rb0 = *(const float4*)(Bp + (size_t)bRow*N);
    rb1 = *(const float4*)(Bp + (size_t)(bRow + 8)*N);
    sts(0);
    __syncthreads();

    float acc[2][8][4] = {};
    const int nk = K >> 4;
    for (int i = 0; i < nk; i++) {
        int buf = i & 1;
        if (i + 1 < nk) {
            ldgA((i + 1)*16);
            const float* Bp2 = Bp + (size_t)(i + 1)*16*N;
            rb0 = *(const float4*)(Bp2 + (size_t)bRow*N);
            rb1 = *(const float4*)(Bp2 + (size_t)(bRow + 8)*N);
        }
        #pragma unroll
        for (int kc = 0; kc < 16; kc += 8) {
            uint32_t af[2][4];
            #pragma unroll
            for (int mi = 0; mi < 2; mi++) {
                int r = wm0 + mi*16 + grp;
                const uint32_t* as = As[buf];
                af[mi][0] = as[r*ASTR + kc + qd];
                af[mi][1] = as[(r + 8)*ASTR + kc + qd];
                af[mi][2] = as[r*ASTR + kc + qd + 4];
                af[mi][3] = as[(r + 8)*ASTR + kc + qd + 4];
            }
            uint32_t bf[8][2];
            #pragma unroll
            for (int ni = 0; ni < 8; ni++) {
                int c = wn0 + ni*8 + grp;
                const uint32_t* bs = Bs[buf];
                bf[ni][0] = bs[(kc + qd)*BSTR + c];
                bf[ni][1] = bs[(kc + qd + 4)*BSTR + c];
            }
            #pragma unroll
            for (int mi = 0; mi < 2; mi++)
                #pragma unroll
                for (int ni = 0; ni < 8; ni++)
                    mma8(acc[mi][ni], af[mi], bf[ni]);
        }
        if (i + 1 < nk) sts((i + 1) & 1);
        __syncthreads();
    }

    // epilogue: scatter to (b, n, t, h, w) + residual
    #pragma unroll
    for (int mi = 0; mi < 2; mi++) {
        #pragma unroll
        for (int half = 0; half < 2; half++) {
            int m  = bm + wm0 + mi*16 + grp + half*8;
            int sI = m >> 4, t = m & 15;
            int b  = sI >> 10, hw = sI & 1023;
            #pragma unroll
            for (int ni = 0; ni < 8; ni++) {
                int c = bn + wn0 + ni*8 + 2*qd;
                #pragma unroll
                for (int l = 0; l < 2; l++) {
                    int n = c + l;
                    out[((size_t)(b*CC + n)*TT + t)*(HH*WW) + hw] =
                        acc[mi][ni][half*2 + l] + res1[(size_t)m*CC + n];
                }
            }
        }
    }
}

// ---------------- launch ----------------
extern "C" void kernel_launch(void* const* d_in, const int* in_sizes, int n_in,
                              void* d_out, int out_size)
{
    (void)in_sizes; (void)n_in; (void)out_size;
    const float* x     = (const float*)d_in[0];
    const int*   fr    = (const int*)  d_in[1];
    const float* gnorm = (const float*)d_in[2];
    const float* Wq    = (const float*)d_in[3];
    const float* Wkv   = (const float*)d_in[4];
    const float* Wo    = (const float*)d_in[5];
    const float* pos   = (const float*)d_in[6];
    const float* fre   = (const float*)d_in[7];
    const float* w1    = (const float*)d_in[8];
    const float* b1    = (const float*)d_in[9];
    const float* w2    = (const float*)d_in[10];
    const float* b2    = (const float*)d_in[11];
    const float* w3    = (const float*)d_in[12];
    const float* b3    = (const float*)d_in[13];
    const float* Win   = (const float*)d_in[14];
    const float* chang = (const float*)d_in[15];
    const float* Wout  = (const float*)d_in[16];
    float* out = (float*)d_out;

    bias_kernel<<<256, 256>>>(w1, b1, w2, b2, w3, b3);
    woutg_kernel<<<(KP2*CC + 255)/256, 256>>>(Wout, chang);
    embed_norm_kernel<<<dim3(CC/16, HH, BB), 256>>>(x, fr, gnorm, pos, fre);
    // q = xn @ Wq
    gemm_tf32_kernel<<<dim3(CC/128, MM/128), 256>>>(CC, CC, OFF_XN, Wq, -1, OFF_Q);
    // kv = xn @ Wkv
    gemm_tf32_kernel<<<dim3(2*CC/128, MM/128), 256>>>(2*CC, CC, OFF_XN, Wkv, -1, OFF_KV);
    attn_kernel<<<SS*HEADS, 128>>>();
    // res1 = o @ Wo + xt
    gemm_tf32_kernel<<<dim3(CC/128, MM/128), 256>>>(CC, CC, OFF_O, Wo,
                                                    (long long)OFF_XT, OFF_RES1);
    // glu = (res1 @ Win)[:FF] * gelu((res1 @ Win)[FF:])
    gemm_glu_tf32_kernel<<<dim3((FF + 63)/64, MM/128), 256>>>(Win);
    stats_kernel<<<MM, 128>>>();
    gemm_final_tf32_kernel<<<dim3(CC/128, MM/128), 256>>>(out);
}

// round 4
// speedup vs baseline: 2.1223x; 1.1352x over previous
#include <cuda_runtime.h>
#include <math.h>
#include <stdint.h>

// ---------------- problem constants ----------------
#define BB    2
#define CC    512
#define TT    16
#define HH    32
#define WW    32
#define SS    (BB*HH*WW)       // 2048
#define MM    (SS*TT)          // 32768
#define HEADS 8
#define DH    64
#define FF    1365             // inner_ff
#define FF2   2730
#define FHALF 683
#define KP2   1376             // FF padded to multiple of 16
#define NWIN  1408             // padded glu half width (22*64)

// ---------------- scratch arena (lifetime-aliased) ----------------
#define AUNIT (MM*CC)                       // 16,777,216 floats
__device__ float g_arena[6*(size_t)AUNIT];  // ~402 MB
#define OFF_XT   ((size_t)0)
#define OFF_XN   ((size_t)AUNIT)
#define OFF_RES1 ((size_t)AUNIT)            // aliases xn (dead after qkv gemm)
#define OFF_QKV  ((size_t)2*AUNIT)          // [M][1536]: q|k|v
#define OFF_GLU  ((size_t)2*AUNIT)          // aliases qkv (dead after attn)
#define OFF_O    ((size_t)5*AUNIT)

__device__ float  g_bias[HEADS*TT*TT];      // (8,16,16)
__device__ float  g_wqkv[CC*1536];          // tf32 [k][q|kv]
__device__ float  g_wo2 [CC*CC];            // tf32 Wo
__device__ float  g_win1[CC*NWIN];          // tf32 Win half1, zero-padded
__device__ float  g_win2[CC*NWIN];          // tf32 Win half2, zero-padded
__device__ float  g_wout[KP2*CC];           // tf32 chan_g-folded Wout
__device__ float2 g_stats[MM];              // per-row (mean, rstd) for channel LN

// ---------------- helpers ----------------
__device__ __forceinline__ uint32_t f2tf(float f) {
    uint32_t u;
    asm("cvt.rna.tf32.f32 %0, %1;" : "=r"(u) : "f"(f));
    return u;
}
__device__ __forceinline__ float f2tff(float f) {
    return __uint_as_float(f2tf(f));
}
__device__ __forceinline__ void mma8(float* d, const uint32_t* a, const uint32_t* b) {
    asm volatile("mma.sync.aligned.m16n8k8.row.col.f32.tf32.tf32.f32 "
        "{%0,%1,%2,%3},{%4,%5,%6,%7},{%8,%9},{%0,%1,%2,%3};"
        : "+f"(d[0]), "+f"(d[1]), "+f"(d[2]), "+f"(d[3])
        : "r"(a[0]), "r"(a[1]), "r"(a[2]), "r"(a[3]), "r"(b[0]), "r"(b[1]));
}
__device__ __forceinline__ uint32_t s2u(const void* p) {
    return (uint32_t)__cvta_generic_to_shared(p);
}
__device__ __forceinline__ void cpa16(uint32_t d, const void* s) {
    asm volatile("cp.async.cg.shared.global [%0], [%1], 16;" :: "r"(d), "l"(s));
}
#define CP_COMMIT asm volatile("cp.async.commit_group;")
#define CP_WAIT0  asm volatile("cp.async.wait_group 0;")

#define ASTR 20     // A smem row stride
#define BSTR 136    // B smem row stride (128-wide tiles)
#define BSTR2 72    // B smem row stride (64-wide tiles)

// ---------------- weight prep: tf32 conversion + packing ----------------
#define PN1 (CC*1536)
#define PN2 (CC*CC)
#define PN3 (CC*NWIN)
#define PTOT (PN1 + PN2 + 2*PN3 + KP2*CC)
__global__ void __launch_bounds__(256) prep_kernel(
    const float* __restrict__ Wq, const float* __restrict__ Wkv,
    const float* __restrict__ Wo, const float* __restrict__ Win,
    const float* __restrict__ chang, const float* __restrict__ Wout)
{
    int idx = blockIdx.x*256 + threadIdx.x;
    if (idx < PN1) {
        int k = idx/1536, n = idx - k*1536;
        float v = (n < 512) ? Wq[k*512 + n] : Wkv[k*1024 + (n - 512)];
        g_wqkv[idx] = f2tff(v);
        return;
    }
    idx -= PN1;
    if (idx < PN2) { g_wo2[idx] = f2tff(Wo[idx]); return; }
    idx -= PN2;
    if (idx < PN3) {
        int k = idx/NWIN, n = idx - k*NWIN;
        g_win1[idx] = (n < FF) ? f2tff(Win[(size_t)k*FF2 + n]) : 0.f;
        return;
    }
    idx -= PN3;
    if (idx < PN3) {
        int k = idx/NWIN, n = idx - k*NWIN;
        g_win2[idx] = (n < FF) ? f2tff(Win[(size_t)k*FF2 + FF + n]) : 0.f;
        return;
    }
    idx -= PN3;
    if (idx < KP2*CC) {
        int k = idx >> 9, n = idx & 511;
        g_wout[idx] = (k < FF) ? f2tff(chang[k] * Wout[k*CC + n]) : 0.f;
    }
}

// ---------------- relative position bias MLP ----------------
__global__ void __launch_bounds__(256) bias_kernel(
    const float* __restrict__ w1, const float* __restrict__ b1,
    const float* __restrict__ w2, const float* __restrict__ b2,
    const float* __restrict__ w3, const float* __restrict__ b3)
{
    __shared__ float h1[256];
    __shared__ float h2[256];
    int i = blockIdx.x >> 4, j = blockIdx.x & 15;
    int tid = threadIdx.x;
    float r   = (float)(i - j);
    float sgn = (r > 0.f) ? 1.f : ((r < 0.f) ? -1.f : 0.f);
    float rel = sgn * logf(fabsf(r) + 1.f);
    float a = rel * w1[tid] + b1[tid];
    h1[tid] = a / (1.f + expf(-a));             // silu
    __syncthreads();
    float acc = b2[tid];
    for (int k = 0; k < 256; k++) acc += h1[k] * w2[k*256 + tid];
    h2[tid] = acc / (1.f + expf(-acc));
    __syncthreads();
    if (tid < 8) {
        float o = b3[tid];
        for (int k = 0; k < 256; k++) o += h2[k] * w3[k*8 + tid];
        g_bias[tid*256 + blockIdx.x] = o;       // [h][i*16+j]
    }
}

// ---------------- transpose + embed + LayerNorm over t ----------------
__global__ void __launch_bounds__(256) embed_norm_kernel(
    const float* __restrict__ x, const int* __restrict__ fr_p,
    const float* __restrict__ gnorm, const float* __restrict__ pos_emb,
    const float* __restrict__ fr_emb)
{
    float* xt = g_arena + OFF_XT;
    float* xn = g_arena + OFF_XN;
    __shared__ float sx[16*513 + 32];
    __shared__ float pes[256];          // [t][c_local]
    int c0 = blockIdx.x * 16;
    int h  = blockIdx.y;
    int b  = blockIdx.z;
    int tid = threadIdx.x;
    int fr = fr_p[0];
    {
        int t = tid >> 4, c = tid & 15;
        pes[tid] = pos_emb[t*CC + c0 + c] + fr_emb[(fr-1)*CC + c0 + c];
    }
    __syncthreads();
    #pragma unroll
    for (int it = 0; it < 32; it++) {
        int idx = tid + it*256;            // c*512 + t*32 + w  (w fastest)
        int c = idx >> 9;
        int rr = idx & 511;
        int t = rr >> 5;
        int w = rr & 31;
        float xv = x[((size_t)((b*CC + c0 + c)*TT + t))*(HH*WW) + h*WW + w];
        sx[c*513 + t*32 + w] = xv + pes[t*16 + c];
    }
    __syncthreads();
    #pragma unroll
    for (int p = 0; p < 2; p++) {
        int pidx = tid + p*256;
        int c = pidx & 15;
        int w = pidx >> 4;
        int s = (b*HH + h)*WW + w;
        float sum = 0.f, ssq = 0.f;
        #pragma unroll
        for (int t = 0; t < 16; t++) {
            float v = sx[c*513 + t*32 + w];
            sum += v; ssq += v*v;
        }
        float mean = sum * (1.f/16.f);
        float var  = ssq * (1.f/16.f) - mean*mean;
        float rs   = rsqrtf(fmaxf(var, 1e-5f));
        float g    = gnorm[c0 + c];
        #pragma unroll
        for (int t = 0; t < 16; t++) {
            float v = sx[c*513 + t*32 + w];
            size_t addr = (size_t)(s*TT + t)*CC + c0 + c;
            xn[addr] = f2tff((v - mean) * rs * g);   // pre-rounded for GEMM A
            xt[addr] = v - pes[t*16 + c];            // raw x (no embeddings)
        }
    }
}

// ---------------- generic TF32 GEMM, cp.async, 128x128x16 ----------------
// A and B already tf32-rounded in global memory.
__global__ void __launch_bounds__(256) gemm_async_kernel(
    int N, int K, int aSel, int bSel, int resSel, int cSel)
{
    const float* A   = g_arena + (aSel == 0 ? OFF_XN : OFF_O);
    const float* Bg  = (bSel == 0) ? g_wqkv : g_wo2;
    const float* res = resSel ? (g_arena + OFF_XT) : (const float*)0;
    float* C = g_arena + (cSel == 0 ? OFF_QKV : OFF_RES1);

    __shared__ float As[2][128*ASTR];
    __shared__ float Bs[2][16*BSTR];

    int bm = blockIdx.y * 128;
    int bn = blockIdx.x * 128;
    int tid = threadIdx.x;
    int lane = tid & 31, warp = tid >> 5;
    int wm0 = (warp >> 1) * 32, wn0 = (warp & 1) * 64;
    int grp = lane >> 2, qd = lane & 3;

    int ar0 = tid >> 2, ak4 = (tid & 3) * 4;
    int br0 = tid >> 5, bn4 = (tid & 31) * 4;
    const float* Asrc0 = A + (size_t)(bm + ar0)*K + ak4;
    const float* Asrc1 = A + (size_t)(bm + ar0 + 64)*K + ak4;
    const float* Bsrc0 = Bg + (size_t)br0*N + bn + bn4;
    const float* Bsrc1 = Bg + (size_t)(br0 + 8)*N + bn + bn4;
    uint32_t sAb = s2u(&As[0][0]);
    uint32_t sBb = s2u(&Bs[0][0]);
    uint32_t dA0 = (uint32_t)((ar0*ASTR + ak4)*4);
    uint32_t dA1 = (uint32_t)(((ar0 + 64)*ASTR + ak4)*4);
    uint32_t dB0 = (uint32_t)((br0*BSTR + bn4)*4);
    uint32_t dB1 = (uint32_t)(((br0 + 8)*BSTR + bn4)*4);

    auto ldg = [&](int buf, int kt) {
        uint32_t a = sAb + buf*(128*ASTR*4);
        uint32_t b = sBb + buf*(16*BSTR*4);
        cpa16(a + dA0, Asrc0 + kt*16);
        cpa16(a + dA1, Asrc1 + kt*16);
        cpa16(b + dB0, Bsrc0 + (size_t)kt*16*N);
        cpa16(b + dB1, Bsrc1 + (size_t)kt*16*N);
    };

    float acc[2][8][4] = {};
    int nk = K >> 4;
    ldg(0, 0); CP_COMMIT;
    CP_WAIT0; __syncthreads();
    for (int i = 0; i < nk; i++) {
        int buf = i & 1;
        if (i + 1 < nk) { ldg((i + 1) & 1, i + 1); CP_COMMIT; }
        #pragma unroll
        for (int kc = 0; kc < 16; kc += 8) {
            uint32_t af[2][4];
            #pragma unroll
            for (int mi = 0; mi < 2; mi++) {
                int r = wm0 + mi*16 + grp;
                const float* as = As[buf];
                af[mi][0] = __float_as_uint(as[r*ASTR + kc + qd]);
                af[mi][1] = __float_as_uint(as[(r + 8)*ASTR + kc + qd]);
                af[mi][2] = __float_as_uint(as[r*ASTR + kc + qd + 4]);
                af[mi][3] = __float_as_uint(as[(r + 8)*ASTR + kc + qd + 4]);
            }
            uint32_t bf[8][2];
            #pragma unroll
            for (int ni = 0; ni < 8; ni++) {
                int c = wn0 + ni*8 + grp;
                const float* bs = Bs[buf];
                bf[ni][0] = __float_as_uint(bs[(kc + qd)*BSTR + c]);
                bf[ni][1] = __float_as_uint(bs[(kc + qd + 4)*BSTR + c]);
            }
            #pragma unroll
            for (int mi = 0; mi < 2; mi++)
                #pragma unroll
                for (int ni = 0; ni < 8; ni++)
                    mma8(acc[mi][ni], af[mi], bf[ni]);
        }
        CP_WAIT0;
        __syncthreads();
    }

    #pragma unroll
    for (int mi = 0; mi < 2; mi++) {
        #pragma unroll
        for (int ni = 0; ni < 8; ni++) {
            int r = bm + wm0 + mi*16 + grp;
            int c = bn + wn0 + ni*8 + 2*qd;
            float* d = acc[mi][ni];
            float2 v0 = make_float2(d[0], d[1]);
            float2 v1 = make_float2(d[2], d[3]);
            if (res) {
                float2 r0 = *(const float2*)(res + (size_t)r*N + c);
                float2 r1 = *(const float2*)(res + (size_t)(r + 8)*N + c);
                v0.x += r0.x; v0.y += r0.y;
                v1.x += r1.x; v1.y += r1.y;
            }
            *(float2*)(C + (size_t)r*N + c)       = v0;
            *(float2*)(C + (size_t)(r + 8)*N + c) = v1;
        }
    }
}

// ---------------- attention: one block per (s, head) ----------------
__global__ void __launch_bounds__(128) attn_kernel()
{
    const float* qkv = g_arena + OFF_QKV;
    float*       o   = g_arena + OFF_O;
    __shared__ float qs[16*65], ks[16*65], vs[16*65], sm[16*17];
    int s  = blockIdx.x >> 3;
    int hd = blockIdx.x & 7;
    int tid = threadIdx.x;
    for (int idx = tid; idx < 1024; idx += 128) {
        int t = idx >> 6, d = idx & 63;
        size_t base = (size_t)(s*16 + t)*1536 + hd*64 + d;
        qs[t*65 + d] = qkv[base];
        ks[t*65 + d] = qkv[base + 512];
        vs[t*65 + d] = qkv[base + 1024];
    }
    __syncthreads();
    for (int e = tid; e < 256; e += 128) {
        int i = e >> 4, j = e & 15;
        float acc = 0.f;
        #pragma unroll
        for (int d = 0; d < 64; d++) acc += qs[i*65 + d] * ks[j*65 + d];
        sm[i*17 + j] = acc * 0.125f + g_bias[hd*256 + i*16 + j];
    }
    __syncthreads();
    if (tid < 16) {
        int i = tid;
        float mx = -1e30f;
        for (int j = 0; j < 16; j++) mx = fmaxf(mx, sm[i*17 + j]);
        float ssum = 0.f;
        for (int j = 0; j < 16; j++) { float e2 = expf(sm[i*17+j] - mx); sm[i*17+j] = e2; ssum += e2; }
        float inv = 1.f / ssum;
        for (int j = 0; j < 16; j++) sm[i*17 + j] *= inv;
    }
    __syncthreads();
    for (int e = tid; e < 1024; e += 128) {
        int i = e >> 6, d = e & 63;
        float acc = 0.f;
        #pragma unroll
        for (int j = 0; j < 16; j++) acc += sm[i*17 + j] * vs[j*65 + d];
        o[(size_t)(s*16 + i)*512 + hd*64 + d] = f2tff(acc);   // pre-rounded for GEMM A
    }
}

// ---------------- Win GEMM fused with GeGLU: 128x64, cp.async ----------------
__global__ void __launch_bounds__(256) gemm_glu_kernel()
{
    const float* A   = g_arena + OFF_RES1;     // raw fp32
    float*       glu = g_arena + OFF_GLU;

    __shared__ float As[2][128*ASTR];
    __shared__ float B1[2][16*BSTR2];
    __shared__ float B2[2][16*BSTR2];

    int bm = blockIdx.y * 128;
    int bn = blockIdx.x * 64;
    int tid = threadIdx.x;
    int lane = tid & 31, warp = tid >> 5;
    int wm0 = (warp >> 1) * 32, wn0 = (warp & 1) * 32;
    int grp = lane >> 2, qd = lane & 3;

    int ar0 = tid >> 2, ak4 = (tid & 3) * 4;
    int br0 = tid >> 4, bn4 = (tid & 15) * 4;     // 16 rows x 16 f4 per half
    const float* Asrc0 = A + (size_t)(bm + ar0)*512 + ak4;
    const float* Asrc1 = A + (size_t)(bm + ar0 + 64)*512 + ak4;
    const float* B1src = g_win1 + (size_t)br0*NWIN + bn + bn4;
    const float* B2src = g_win2 + (size_t)br0*NWIN + bn + bn4;
    uint32_t sAb = s2u(&As[0][0]);
    uint32_t sB1 = s2u(&B1[0][0]);
    uint32_t sB2 = s2u(&B2[0][0]);
    uint32_t dA0 = (uint32_t)((ar0*ASTR + ak4)*4);
    uint32_t dA1 = (uint32_t)(((ar0 + 64)*ASTR + ak4)*4);
    uint32_t dB  = (uint32_t)((br0*BSTR2 + bn4)*4);

    auto ldg = [&](int buf, int kt) {
        uint32_t a = sAb + buf*(128*ASTR*4);
        cpa16(a + dA0, Asrc0 + kt*16);
        cpa16(a + dA1, Asrc1 + kt*16);
        cpa16(sB1 + buf*(16*BSTR2*4) + dB, B1src + (size_t)kt*16*NWIN);
        cpa16(sB2 + buf*(16*BSTR2*4) + dB, B2src + (size_t)kt*16*NWIN);
    };

    float a1[2][4][4] = {}, a2[2][4][4] = {};
    const int nk = 512 >> 4;
    ldg(0, 0); CP_COMMIT;
    CP_WAIT0; __syncthreads();
    for (int i = 0; i < nk; i++) {
        int buf = i & 1;
        if (i + 1 < nk) { ldg((i + 1) & 1, i + 1); CP_COMMIT; }
        #pragma unroll
        for (int kc = 0; kc < 16; kc += 8) {
            uint32_t af[2][4];
            #pragma unroll
            for (int mi = 0; mi < 2; mi++) {
                int r = wm0 + mi*16 + grp;
                const float* as = As[buf];
                af[mi][0] = f2tf(as[r*ASTR + kc + qd]);
                af[mi][1] = f2tf(as[(r + 8)*ASTR + kc + qd]);
                af[mi][2] = f2tf(as[r*ASTR + kc + qd + 4]);
                af[mi][3] = f2tf(as[(r + 8)*ASTR + kc + qd + 4]);
            }
            uint32_t bf1[4][2], bf2[4][2];
            #pragma unroll
            for (int ni = 0; ni < 4; ni++) {
                int c = wn0 + ni*8 + grp;
                bf1[ni][0] = __float_as_uint(B1[buf][(kc + qd)*BSTR2 + c]);
                bf1[ni][1] = __float_as_uint(B1[buf][(kc + qd + 4)*BSTR2 + c]);
                bf2[ni][0] = __float_as_uint(B2[buf][(kc + qd)*BSTR2 + c]);
                bf2[ni][1] = __float_as_uint(B2[buf][(kc + qd + 4)*BSTR2 + c]);
            }
            #pragma unroll
            for (int mi = 0; mi < 2; mi++)
                #pragma unroll
                for (int ni = 0; ni < 4; ni++) {
                    mma8(a1[mi][ni], af[mi], bf1[ni]);
                    mma8(a2[mi][ni], af[mi], bf2[ni]);
                }
        }
        CP_WAIT0;
        __syncthreads();
    }

    #pragma unroll
    for (int mi = 0; mi < 2; mi++) {
        #pragma unroll
        for (int ni = 0; ni < 4; ni++) {
            int c = bn + wn0 + ni*8 + 2*qd;
            #pragma unroll
            for (int half = 0; half < 2; half++) {
                int r = bm + wm0 + mi*16 + grp + half*8;
                #pragma unroll
                for (int l = 0; l < 2; l++) {
                    int col = c + l;
                    if (col < FF) {
                        float y1 = a1[mi][ni][half*2 + l];
                        float gt = a2[mi][ni][half*2 + l];
                        float gl = 0.5f * gt * (1.f + erff(gt * 0.70710678118654752f));
                        glu[(size_t)r*FF + col] = y1 * gl;
                    }
                }
            }
        }
    }
}

// ---------------- time-shift + channel LN: stats only ----------------
__device__ __forceinline__ float shifted_val(const float* glu, int m, int t, int f)
{
    if (f < FHALF) return glu[(size_t)m*FF + f];
    return (t > 0) ? glu[(size_t)(m-1)*FF + f] : 0.f;
}

__global__ void __launch_bounds__(128) stats_kernel()
{
    const float* glu = g_arena + OFF_GLU;
    int m = blockIdx.x;
    int t = m & 15;
    int tid = threadIdx.x;
    float s = 0.f, ss = 0.f;
    for (int f = tid; f < FF; f += 128) {
        float v = shifted_val(glu, m, t, f);
        s += v; ss += v*v;
    }
    #pragma unroll
    for (int o = 16; o; o >>= 1) {
        s  += __shfl_down_sync(0xffffffffu, s, o);
        ss += __shfl_down_sync(0xffffffffu, ss, o);
    }
    __shared__ float rA[4], rB[4];
    int wid = tid >> 5, lane = tid & 31;
    if (lane == 0) { rA[wid] = s; rB[wid] = ss; }
    __syncthreads();
    if (tid == 0) {
        float S = 0.f, SQ = 0.f;
        for (int i = 0; i < 4; i++) { S += rA[i]; SQ += rB[i]; }
        float mean = S * (1.f/FF);
        float var  = SQ * (1.f/FF) - mean*mean;
        g_stats[m] = make_float2(mean, rsqrtf(fmaxf(var, 1e-5f)));
    }
}

// ---------------- final GEMM: staged-A (shift+norm), cp.async B ----------------
__global__ void __launch_bounds__(256) gemm_final_kernel(float* __restrict__ out)
{
    const float* glu  = g_arena + OFF_GLU;
    const float* res1 = g_arena + OFF_RES1;
    const int N = CC, K = KP2;

    __shared__ float As[2][128*ASTR];
    __shared__ float Bs[2][16*BSTR];

    int bm = blockIdx.y * 128;
    int bn = blockIdx.x * 128;
    int tid = threadIdx.x;
    int lane = tid & 31, warp = tid >> 5;
    int wm0 = (warp >> 1) * 32, wn0 = (warp & 1) * 64;
    int grp = lane >> 2, qd = lane & 3;
    int aRow = tid >> 1, aCol = (tid & 1) * 8;
    int br0 = tid >> 5, bn4 = (tid & 31) * 4;

    int    am   = bm + aRow;
    int    at   = am & 15;
    float2 st   = g_stats[am];
    float  mean = st.x, rstd = st.y;
    const float* gRow  = glu + (size_t)am*FF;
    const float* gPrev = glu + (size_t)(am - 1)*FF;  // only read when at>0
    const float* Bsrc0 = g_wout + (size_t)br0*N + bn + bn4;
    const float* Bsrc1 = g_wout + (size_t)(br0 + 8)*N + bn + bn4;
    uint32_t sBb = s2u(&Bs[0][0]);
    uint32_t dB0 = (uint32_t)((br0*BSTR + bn4)*4);
    uint32_t dB1 = (uint32_t)(((br0 + 8)*BSTR + bn4)*4);

    float ra[8];
    auto ldgA = [&](int kt) {
        int k0 = kt*16;
        #pragma unroll
        for (int j = 0; j < 8; j++) {
            int k = k0 + aCol + j;
            float v = 0.f;
            if (k < FF) {
                float raw;
                if (k < FHALF)   raw = gRow[k];
                else if (at > 0) raw = gPrev[k];
                else             raw = 0.f;
                v = (raw - mean) * rstd;
            }
            ra[j] = v;
        }
    };
    auto stsA = [&](int buf) {
        float* a = As[buf] + aRow*ASTR + aCol;
        #pragma unroll
        for (int j = 0; j < 8; j++) a[j] = f2tff(ra[j]);
    };
    auto ldgB = [&](int buf, int kt) {
        uint32_t b = sBb + buf*(16*BSTR*4);
        cpa16(b + dB0, Bsrc0 + (size_t)kt*16*N);
        cpa16(b + dB1, Bsrc1 + (size_t)kt*16*N);
    };

    float acc[2][8][4] = {};
    const int nk = K >> 4;
    ldgA(0); ldgB(0, 0); CP_COMMIT;
    stsA(0);
    CP_WAIT0; __syncthreads();
    for (int i = 0; i < nk; i++) {
        int buf = i & 1;
        if (i + 1 < nk) { ldgA(i + 1); ldgB((i + 1) & 1, i + 1); CP_COMMIT; }
        #pragma unroll
        for (int kc = 0; kc < 16; kc += 8) {
            uint32_t af[2][4];
            #pragma unroll
            for (int mi = 0; mi < 2; mi++) {
                int r = wm0 + mi*16 + grp;
                const float* as = As[buf];
                af[mi][0] = __float_as_uint(as[r*ASTR + kc + qd]);
                af[mi][1] = __float_as_uint(as[(r + 8)*ASTR + kc + qd]);
                af[mi][2] = __float_as_uint(as[r*ASTR + kc + qd + 4]);
                af[mi][3] = __float_as_uint(as[(r + 8)*ASTR + kc + qd + 4]);
            }
            uint32_t bf[8][2];
            #pragma unroll
            for (int ni = 0; ni < 8; ni++) {
                int c = wn0 + ni*8 + grp;
                const float* bs = Bs[buf];
                bf[ni][0] = __float_as_uint(bs[(kc + qd)*BSTR + c]);
                bf[ni][1] = __float_as_uint(bs[(kc + qd + 4)*BSTR + c]);
            }
            #pragma unroll
            for (int mi = 0; mi < 2; mi++)
                #pragma unroll
                for (int ni = 0; ni < 8; ni++)
                    mma8(acc[mi][ni], af[mi], bf[ni]);
        }
        if (i + 1 < nk) stsA((i + 1) & 1);
        CP_WAIT0;
        __syncthreads();
    }

    // epilogue: scatter to (b, n, t, h, w) + residual
    #pragma unroll
    for (int mi = 0; mi < 2; mi++) {
        #pragma unroll
        for (int half = 0; half < 2; half++) {
            int m  = bm + wm0 + mi*16 + grp + half*8;
            int sI = m >> 4, t = m & 15;
            int b  = sI >> 10, hw = sI & 1023;
            #pragma unroll
            for (int ni = 0; ni < 8; ni++) {
                int c = bn + wn0 + ni*8 + 2*qd;
                #pragma unroll
                for (int l = 0; l < 2; l++) {
                    int n = c + l;
                    out[((size_t)(b*CC + n)*TT + t)*(HH*WW) + hw] =
                        acc[mi][ni][half*2 + l] + res1[(size_t)m*CC + n];
                }
            }
        }
    }
}

// ---------------- launch ----------------
extern "C" void kernel_launch(void* const* d_in, const int* in_sizes, int n_in,
                              void* d_out, int out_size)
{
    (void)in_sizes; (void)n_in; (void)out_size;
    const float* x     = (const float*)d_in[0];
    const int*   fr    = (const int*)  d_in[1];
    const float* gnorm = (const float*)d_in[2];
    const float* Wq    = (const float*)d_in[3];
    const float* Wkv   = (const float*)d_in[4];
    const float* Wo    = (const float*)d_in[5];
    const float* pos   = (const float*)d_in[6];
    const float* fre   = (const float*)d_in[7];
    const float* w1    = (const float*)d_in[8];
    const float* b1    = (const float*)d_in[9];
    const float* w2    = (const float*)d_in[10];
    const float* b2    = (const float*)d_in[11];
    const float* w3    = (const float*)d_in[12];
    const float* b3    = (const float*)d_in[13];
    const float* Win   = (const float*)d_in[14];
    const float* chang = (const float*)d_in[15];
    const float* Wout  = (const float*)d_in[16];
    float* out = (float*)d_out;

    prep_kernel<<<(PTOT + 255)/256, 256>>>(Wq, Wkv, Wo, Win, chang, Wout);
    bias_kernel<<<256, 256>>>(w1, b1, w2, b2, w3, b3);
    embed_norm_kernel<<<dim3(CC/16, HH, BB), 256>>>(x, fr, gnorm, pos, fre);
    // qkv = xn @ [Wq|Wkv]
    gemm_async_kernel<<<dim3(1536/128, MM/128), 256>>>(1536, CC, 0, 0, 0, 0);
    attn_kernel<<<SS*HEADS, 128>>>();
    // res1 = o @ Wo + xt
    gemm_async_kernel<<<dim3(CC/128, MM/128), 256>>>(CC, CC, 1, 1, 1, 1);
    // glu = (res1 @ Win)[:FF] * gelu((res1 @ Win)[FF:])
    gemm_glu_kernel<<<dim3(NWIN/64, MM/128), 256>>>();
    stats_kernel<<<MM, 128>>>();
    gemm_final_kernel<<<dim3(CC/128, MM/128), 256>>>(out);
}

// round 5
// speedup vs baseline: 2.2710x; 1.0700x over previous
#include <cuda_runtime.h>
#include <math.h>
#include <stdint.h>

// ---------------- problem constants ----------------
#define BB    2
#define CC    512
#define TT    16
#define HH    32
#define WW    32
#define SS    (BB*HH*WW)       // 2048
#define MM    (SS*TT)          // 32768
#define HEADS 8
#define DH    64
#define FF    1365             // inner_ff
#define FF2   2730
#define FHALF 683
#define KP2   1376             // FF padded to multiple of 16
#define NWIN  1408             // padded glu half width (22*64)

// ---------------- scratch arena (lifetime-aliased) ----------------
#define AUNIT (MM*CC)                       // 16,777,216 floats
__device__ float g_arena[6*(size_t)AUNIT];  // ~402 MB
#define OFF_XT   ((size_t)0)
#define OFF_XN   ((size_t)AUNIT)
#define OFF_RES1 ((size_t)AUNIT)            // aliases xn (dead after qkv gemm)
#define OFF_QKV  ((size_t)2*AUNIT)          // [M][1536]: q|k|v
#define OFF_GLU  ((size_t)2*AUNIT)          // aliases qkv (dead after attn)
#define OFF_O    ((size_t)5*AUNIT)

__device__ float  g_bias[HEADS*TT*TT];      // (8,16,16)
__device__ float  g_wqkv[CC*1536];          // tf32 [k][q|kv]
__device__ float  g_wo2 [CC*CC];            // tf32 Wo
__device__ float  g_win1[CC*NWIN];          // tf32 Win half1, zero-padded
__device__ float  g_win2[CC*NWIN];          // tf32 Win half2, zero-padded
__device__ float  g_wout[KP2*CC];           // tf32 chan_g-folded Wout
__device__ float2 g_stats[MM];              // per-row (mean, rstd) for channel LN

// ---------------- helpers ----------------
__device__ __forceinline__ uint32_t f2tf(float f) {
    uint32_t u;
    asm("cvt.rna.tf32.f32 %0, %1;" : "=r"(u) : "f"(f));
    return u;
}
__device__ __forceinline__ float f2tff(float f) {
    return __uint_as_float(f2tf(f));
}
__device__ __forceinline__ void mma8(float* d, const uint32_t* a, const uint32_t* b) {
    asm volatile("mma.sync.aligned.m16n8k8.row.col.f32.tf32.tf32.f32 "
        "{%0,%1,%2,%3},{%4,%5,%6,%7},{%8,%9},{%0,%1,%2,%3};"
        : "+f"(d[0]), "+f"(d[1]), "+f"(d[2]), "+f"(d[3])
        : "r"(a[0]), "r"(a[1]), "r"(a[2]), "r"(a[3]), "r"(b[0]), "r"(b[1]));
}
__device__ __forceinline__ uint32_t s2u(const void* p) {
    return (uint32_t)__cvta_generic_to_shared(p);
}
__device__ __forceinline__ void cpa16(uint32_t d, const void* s) {
    asm volatile("cp.async.cg.shared.global [%0], [%1], 16;" :: "r"(d), "l"(s));
}
#define CP_COMMIT asm volatile("cp.async.commit_group;")
#define CP_WAIT0  asm volatile("cp.async.wait_group 0;")
#define CP_WAIT1  asm volatile("cp.async.wait_group 1;")

#define ASTR 20     // A smem row stride (conflict-free frag loads)
#define BSTR 136    // B smem row stride (128-wide tiles)
#define BSTR2 72    // B smem row stride (64-wide tiles)
#define ASZ  (128*ASTR)   // 2560 floats per A buffer
#define BSZ  (16*BSTR)    // 2176 floats per B buffer
#define BSZ2 (16*BSTR2)   // 1152 floats per half-B buffer

// ---------------- weight prep: tf32 conversion + packing ----------------
#define PN1 (CC*1536)
#define PN2 (CC*CC)
#define PN3 (CC*NWIN)
#define PTOT (PN1 + PN2 + 2*PN3 + KP2*CC)
__global__ void __launch_bounds__(256) prep_kernel(
    const float* __restrict__ Wq, const float* __restrict__ Wkv,
    const float* __restrict__ Wo, const float* __restrict__ Win,
    const float* __restrict__ chang, const float* __restrict__ Wout)
{
    int idx = blockIdx.x*256 + threadIdx.x;
    if (idx < PN1) {
        int k = idx/1536, n = idx - k*1536;
        float v = (n < 512) ? Wq[k*512 + n] : Wkv[k*1024 + (n - 512)];
        g_wqkv[idx] = f2tff(v);
        return;
    }
    idx -= PN1;
    if (idx < PN2) { g_wo2[idx] = f2tff(Wo[idx]); return; }
    idx -= PN2;
    if (idx < PN3) {
        int k = idx/NWIN, n = idx - k*NWIN;
        g_win1[idx] = (n < FF) ? f2tff(Win[(size_t)k*FF2 + n]) : 0.f;
        return;
    }
    idx -= PN3;
    if (idx < PN3) {
        int k = idx/NWIN, n = idx - k*NWIN;
        g_win2[idx] = (n < FF) ? f2tff(Win[(size_t)k*FF2 + FF + n]) : 0.f;
        return;
    }
    idx -= PN3;
    if (idx < KP2*CC) {
        int k = idx >> 9, n = idx & 511;
        g_wout[idx] = (k < FF) ? f2tff(chang[k] * Wout[k*CC + n]) : 0.f;
    }
}

// ---------------- relative position bias MLP ----------------
__global__ void __launch_bounds__(256) bias_kernel(
    const float* __restrict__ w1, const float* __restrict__ b1,
    const float* __restrict__ w2, const float* __restrict__ b2,
    const float* __restrict__ w3, const float* __restrict__ b3)
{
    __shared__ float h1[256];
    __shared__ float h2[256];
    int i = blockIdx.x >> 4, j = blockIdx.x & 15;
    int tid = threadIdx.x;
    float r   = (float)(i - j);
    float sgn = (r > 0.f) ? 1.f : ((r < 0.f) ? -1.f : 0.f);
    float rel = sgn * logf(fabsf(r) + 1.f);
    float a = rel * w1[tid] + b1[tid];
    h1[tid] = a / (1.f + expf(-a));             // silu
    __syncthreads();
    float acc = b2[tid];
    for (int k = 0; k < 256; k++) acc += h1[k] * w2[k*256 + tid];
    h2[tid] = acc / (1.f + expf(-acc));
    __syncthreads();
    if (tid < 8) {
        float o = b3[tid];
        for (int k = 0; k < 256; k++) o += h2[k] * w3[k*8 + tid];
        g_bias[tid*256 + blockIdx.x] = o;       // [h][i*16+j]
    }
}

// ---------------- transpose + embed + LayerNorm over t ----------------
__global__ void __launch_bounds__(256) embed_norm_kernel(
    const float* __restrict__ x, const int* __restrict__ fr_p,
    const float* __restrict__ gnorm, const float* __restrict__ pos_emb,
    const float* __restrict__ fr_emb)
{
    float* xt = g_arena + OFF_XT;
    float* xn = g_arena + OFF_XN;
    __shared__ float sx[16*513 + 32];
    __shared__ float pes[256];          // [t][c_local]
    int c0 = blockIdx.x * 16;
    int h  = blockIdx.y;
    int b  = blockIdx.z;
    int tid = threadIdx.x;
    int fr = fr_p[0];
    {
        int t = tid >> 4, c = tid & 15;
        pes[tid] = pos_emb[t*CC + c0 + c] + fr_emb[(fr-1)*CC + c0 + c];
    }
    __syncthreads();
    #pragma unroll
    for (int it = 0; it < 32; it++) {
        int idx = tid + it*256;            // c*512 + t*32 + w  (w fastest)
        int c = idx >> 9;
        int rr = idx & 511;
        int t = rr >> 5;
        int w = rr & 31;
        float xv = x[((size_t)((b*CC + c0 + c)*TT + t))*(HH*WW) + h*WW + w];
        sx[c*513 + t*32 + w] = xv + pes[t*16 + c];
    }
    __syncthreads();
    #pragma unroll
    for (int p = 0; p < 2; p++) {
        int pidx = tid + p*256;
        int c = pidx & 15;
        int w = pidx >> 4;
        int s = (b*HH + h)*WW + w;
        float sum = 0.f, ssq = 0.f;
        #pragma unroll
        for (int t = 0; t < 16; t++) {
            float v = sx[c*513 + t*32 + w];
            sum += v; ssq += v*v;
        }
        float mean = sum * (1.f/16.f);
        float var  = ssq * (1.f/16.f) - mean*mean;
        float rs   = rsqrtf(fmaxf(var, 1e-5f));
        float g    = gnorm[c0 + c];
        #pragma unroll
        for (int t = 0; t < 16; t++) {
            float v = sx[c*513 + t*32 + w];
            size_t addr = (size_t)(s*TT + t)*CC + c0 + c;
            xn[addr] = f2tff((v - mean) * rs * g);   // pre-rounded for GEMM A
            xt[addr] = v - pes[t*16 + c];            // raw x (no embeddings)
        }
    }
}

// ---------------- generic TF32 GEMM, 3-stage cp.async, 128x128x16 ----------------
__global__ void __launch_bounds__(256) gemm_async_kernel(
    int N, int K, int aSel, int bSel, int resSel, int cSel)
{
    const float* A   = g_arena + (aSel == 0 ? OFF_XN : OFF_O);
    const float* Bg  = (bSel == 0) ? g_wqkv : g_wo2;
    const float* res = resSel ? (g_arena + OFF_XT) : (const float*)0;
    float* C = g_arena + (cSel == 0 ? OFF_QKV : OFF_RES1);

    extern __shared__ float smem[];
    float* Asm = smem;              // 3 * ASZ
    float* Bsm = smem + 3*ASZ;      // 3 * BSZ

    int bm = blockIdx.y * 128;
    int bn = blockIdx.x * 128;
    int tid = threadIdx.x;
    int lane = tid & 31, warp = tid >> 5;
    int wm0 = (warp >> 1) * 32, wn0 = (warp & 1) * 64;
    int grp = lane >> 2, qd = lane & 3;

    int ar0 = tid >> 2, ak4 = (tid & 3) * 4;
    int br0 = tid >> 5, bn4 = (tid & 31) * 4;
    const float* Asrc0 = A + (size_t)(bm + ar0)*K + ak4;
    const float* Asrc1 = A + (size_t)(bm + ar0 + 64)*K + ak4;
    const float* Bsrc0 = Bg + (size_t)br0*N + bn + bn4;
    const float* Bsrc1 = Bg + (size_t)(br0 + 8)*N + bn + bn4;
    uint32_t sAb = s2u(Asm);
    uint32_t sBb = s2u(Bsm);
    uint32_t dA0 = (uint32_t)((ar0*ASTR + ak4)*4);
    uint32_t dA1 = (uint32_t)(((ar0 + 64)*ASTR + ak4)*4);
    uint32_t dB0 = (uint32_t)((br0*BSTR + bn4)*4);
    uint32_t dB1 = (uint32_t)(((br0 + 8)*BSTR + bn4)*4);

    auto ldg = [&](int buf, int kt) {
        uint32_t a = sAb + buf*(ASZ*4);
        uint32_t b = sBb + buf*(BSZ*4);
        cpa16(a + dA0, Asrc0 + kt*16);
        cpa16(a + dA1, Asrc1 + kt*16);
        cpa16(b + dB0, Bsrc0 + (size_t)kt*16*N);
        cpa16(b + dB1, Bsrc1 + (size_t)kt*16*N);
    };

    float acc[2][8][4] = {};
    int nk = K >> 4;
    ldg(0, 0); CP_COMMIT;
    ldg(1, 1); CP_COMMIT;
    CP_WAIT1; __syncthreads();
    for (int i = 0; i < nk; i++) {
        int buf; { int m3 = i % 3; buf = m3; }
        const float* as = Asm + buf*ASZ;
        const float* bs = Bsm + buf*BSZ;
        #pragma unroll
        for (int kc = 0; kc < 16; kc += 8) {
            uint32_t af[2][4];
            #pragma unroll
            for (int mi = 0; mi < 2; mi++) {
                int r = wm0 + mi*16 + grp;
                af[mi][0] = __float_as_uint(as[r*ASTR + kc + qd]);
                af[mi][1] = __float_as_uint(as[(r + 8)*ASTR + kc + qd]);
                af[mi][2] = __float_as_uint(as[r*ASTR + kc + qd + 4]);
                af[mi][3] = __float_as_uint(as[(r + 8)*ASTR + kc + qd + 4]);
            }
            uint32_t bf[8][2];
            #pragma unroll
            for (int ni = 0; ni < 8; ni++) {
                int c = wn0 + ni*8 + grp;
                bf[ni][0] = __float_as_uint(bs[(kc + qd)*BSTR + c]);
                bf[ni][1] = __float_as_uint(bs[(kc + qd + 4)*BSTR + c]);
            }
            #pragma unroll
            for (int mi = 0; mi < 2; mi++)
                #pragma unroll
                for (int ni = 0; ni < 8; ni++)
                    mma8(acc[mi][ni], af[mi], bf[ni]);
        }
        if (i + 2 < nk) { ldg((i + 2) % 3, i + 2); CP_COMMIT; CP_WAIT1; }
        else CP_WAIT0;
        __syncthreads();
    }

    #pragma unroll
    for (int mi = 0; mi < 2; mi++) {
        #pragma unroll
        for (int ni = 0; ni < 8; ni++) {
            int r = bm + wm0 + mi*16 + grp;
            int c = bn + wn0 + ni*8 + 2*qd;
            float* d = acc[mi][ni];
            float2 v0 = make_float2(d[0], d[1]);
            float2 v1 = make_float2(d[2], d[3]);
            if (res) {
                float2 r0 = *(const float2*)(res + (size_t)r*N + c);
                float2 r1 = *(const float2*)(res + (size_t)(r + 8)*N + c);
                v0.x += r0.x; v0.y += r0.y;
                v1.x += r1.x; v1.y += r1.y;
            }
            *(float2*)(C + (size_t)r*N + c)       = v0;
            *(float2*)(C + (size_t)(r + 8)*N + c) = v1;
        }
    }
}

// ---------------- attention: one block per (s, head), float4 I/O ----------------
#define QSTR 68
__global__ void __launch_bounds__(128) attn_kernel()
{
    const float* qkv = g_arena + OFF_QKV;
    float*       o   = g_arena + OFF_O;
    __shared__ float qs[16*QSTR], ks[16*QSTR], vs[16*QSTR], sm[16*17];
    int s  = blockIdx.x >> 3;
    int hd = blockIdx.x & 7;
    int tid = threadIdx.x;
    #pragma unroll
    for (int p = 0; p < 2; p++) {
        int idx = tid + p*128;              // 256 float4 slots
        int t = idx >> 4, d4 = (idx & 15)*4;
        size_t base = ((size_t)(s*16 + t)*1536 + hd*64 + d4) >> 2;
        const float4* q4 = (const float4*)qkv;
        *(float4*)&qs[t*QSTR + d4] = q4[base];
        *(float4*)&ks[t*QSTR + d4] = q4[base + 128];
        *(float4*)&vs[t*QSTR + d4] = q4[base + 256];
    }
    __syncthreads();
    #pragma unroll
    for (int p = 0; p < 2; p++) {
        int e = tid + p*128;
        int i = e >> 4, j = e & 15;
        float acc = 0.f;
        #pragma unroll
        for (int d = 0; d < 64; d++) acc += qs[i*QSTR + d] * ks[j*QSTR + d];
        sm[i*17 + j] = acc * 0.125f + g_bias[hd*256 + i*16 + j];
    }
    __syncthreads();
    if (tid < 16) {
        int i = tid;
        float mx = -1e30f;
        for (int j = 0; j < 16; j++) mx = fmaxf(mx, sm[i*17 + j]);
        float ssum = 0.f;
        for (int j = 0; j < 16; j++) { float e2 = expf(sm[i*17+j] - mx); sm[i*17+j] = e2; ssum += e2; }
        float inv = 1.f / ssum;
        for (int j = 0; j < 16; j++) sm[i*17 + j] *= inv;
    }
    __syncthreads();
    #pragma unroll
    for (int p = 0; p < 2; p++) {
        int e = tid + p*128;                // 256 float4 outputs
        int i = e >> 4, d4 = (e & 15)*4;
        float4 acc = make_float4(0.f, 0.f, 0.f, 0.f);
        #pragma unroll
        for (int j = 0; j < 16; j++) {
            float pj = sm[i*17 + j];
            const float* v = &vs[j*QSTR + d4];
            acc.x += pj * v[0]; acc.y += pj * v[1];
            acc.z += pj * v[2]; acc.w += pj * v[3];
        }
        acc.x = f2tff(acc.x); acc.y = f2tff(acc.y);
        acc.z = f2tff(acc.z); acc.w = f2tff(acc.w);
        *(float4*)&o[(size_t)(s*16 + i)*512 + hd*64 + d4] = acc;
    }
}

// ---------------- Win GEMM fused with GeGLU: 128x64, 3-stage cp.async ----------------
__global__ void __launch_bounds__(256) gemm_glu_kernel()
{
    const float* A   = g_arena + OFF_RES1;     // raw fp32
    float*       glu = g_arena + OFF_GLU;

    extern __shared__ float smem[];
    float* Asm = smem;                  // 3 * ASZ
    float* B1m = smem + 3*ASZ;          // 3 * BSZ2
    float* B2m = smem + 3*ASZ + 3*BSZ2; // 3 * BSZ2

    int bm = blockIdx.y * 128;
    int bn = blockIdx.x * 64;
    int tid = threadIdx.x;
    int lane = tid & 31, warp = tid >> 5;
    int wm0 = (warp >> 1) * 32, wn0 = (warp & 1) * 32;
    int grp = lane >> 2, qd = lane & 3;

    int ar0 = tid >> 2, ak4 = (tid & 3) * 4;
    int br0 = tid >> 4, bn4 = (tid & 15) * 4;
    const float* Asrc0 = A + (size_t)(bm + ar0)*512 + ak4;
    const float* Asrc1 = A + (size_t)(bm + ar0 + 64)*512 + ak4;
    const float* B1src = g_win1 + (size_t)br0*NWIN + bn + bn4;
    const float* B2src = g_win2 + (size_t)br0*NWIN + bn + bn4;
    uint32_t sAb = s2u(Asm);
    uint32_t sB1 = s2u(B1m);
    uint32_t sB2 = s2u(B2m);
    uint32_t dA0 = (uint32_t)((ar0*ASTR + ak4)*4);
    uint32_t dA1 = (uint32_t)(((ar0 + 64)*ASTR + ak4)*4);
    uint32_t dB  = (uint32_t)((br0*BSTR2 + bn4)*4);

    auto ldg = [&](int buf, int kt) {
        uint32_t a = sAb + buf*(ASZ*4);
        cpa16(a + dA0, Asrc0 + kt*16);
        cpa16(a + dA1, Asrc1 + kt*16);
        cpa16(sB1 + buf*(BSZ2*4) + dB, B1src + (size_t)kt*16*NWIN);
        cpa16(sB2 + buf*(BSZ2*4) + dB, B2src + (size_t)kt*16*NWIN);
    };

    float a1[2][4][4] = {}, a2[2][4][4] = {};
    const int nk = 512 >> 4;
    ldg(0, 0); CP_COMMIT;
    ldg(1, 1); CP_COMMIT;
    CP_WAIT1; __syncthreads();
    for (int i = 0; i < nk; i++) {
        int buf = i % 3;
        const float* as = Asm + buf*ASZ;
        const float* b1 = B1m + buf*BSZ2;
        const float* b2 = B2m + buf*BSZ2;
        #pragma unroll
        for (int kc = 0; kc < 16; kc += 8) {
            uint32_t af[2][4];
            #pragma unroll
            for (int mi = 0; mi < 2; mi++) {
                int r = wm0 + mi*16 + grp;
                af[mi][0] = f2tf(as[r*ASTR + kc + qd]);
                af[mi][1] = f2tf(as[(r + 8)*ASTR + kc + qd]);
                af[mi][2] = f2tf(as[r*ASTR + kc + qd + 4]);
                af[mi][3] = f2tf(as[(r + 8)*ASTR + kc + qd + 4]);
            }
            uint32_t bf1[4][2], bf2[4][2];
            #pragma unroll
            for (int ni = 0; ni < 4; ni++) {
                int c = wn0 + ni*8 + grp;
                bf1[ni][0] = __float_as_uint(b1[(kc + qd)*BSTR2 + c]);
                bf1[ni][1] = __float_as_uint(b1[(kc + qd + 4)*BSTR2 + c]);
                bf2[ni][0] = __float_as_uint(b2[(kc + qd)*BSTR2 + c]);
                bf2[ni][1] = __float_as_uint(b2[(kc + qd + 4)*BSTR2 + c]);
            }
            #pragma unroll
            for (int mi = 0; mi < 2; mi++)
                #pragma unroll
                for (int ni = 0; ni < 4; ni++) {
                    mma8(a1[mi][ni], af[mi], bf1[ni]);
                    mma8(a2[mi][ni], af[mi], bf2[ni]);
                }
        }
        if (i + 2 < nk) { ldg((i + 2) % 3, i + 2); CP_COMMIT; CP_WAIT1; }
        else CP_WAIT0;
        __syncthreads();
    }

    #pragma unroll
    for (int mi = 0; mi < 2; mi++) {
        #pragma unroll
        for (int ni = 0; ni < 4; ni++) {
            int c = bn + wn0 + ni*8 + 2*qd;
            #pragma unroll
            for (int half = 0; half < 2; half++) {
                int r = bm + wm0 + mi*16 + grp + half*8;
                #pragma unroll
                for (int l = 0; l < 2; l++) {
                    int col = c + l;
                    if (col < FF) {
                        float y1 = a1[mi][ni][half*2 + l];
                        float gt = a2[mi][ni][half*2 + l];
                        float gl = 0.5f * gt * (1.f + erff(gt * 0.70710678118654752f));
                        glu[(size_t)r*FF + col] = y1 * gl;
                    }
                }
            }
        }
    }
}

// ---------------- time-shift + channel LN: stats only ----------------
__device__ __forceinline__ float shifted_val(const float* glu, int m, int t, int f)
{
    if (f < FHALF) return glu[(size_t)m*FF + f];
    return (t > 0) ? glu[(size_t)(m-1)*FF + f] : 0.f;
}

__global__ void __launch_bounds__(256) stats_kernel()
{
    const float* glu = g_arena + OFF_GLU;
    int m = blockIdx.x;
    int t = m & 15;
    int tid = threadIdx.x;
    float s = 0.f, ss = 0.f;
    for (int f = tid; f < FF; f += 256) {
        float v = shifted_val(glu, m, t, f);
        s += v; ss += v*v;
    }
    #pragma unroll
    for (int o = 16; o; o >>= 1) {
        s  += __shfl_down_sync(0xffffffffu, s, o);
        ss += __shfl_down_sync(0xffffffffu, ss, o);
    }
    __shared__ float rA[8], rB[8];
    int wid = tid >> 5, lane = tid & 31;
    if (lane == 0) { rA[wid] = s; rB[wid] = ss; }
    __syncthreads();
    if (tid == 0) {
        float S = 0.f, SQ = 0.f;
        for (int i = 0; i < 8; i++) { S += rA[i]; SQ += rB[i]; }
        float mean = S * (1.f/FF);
        float var  = SQ * (1.f/FF) - mean*mean;
        g_stats[m] = make_float2(mean, rsqrtf(fmaxf(var, 1e-5f)));
    }
}

// ---------------- final GEMM: staged-A (shift+norm), cp.async B ----------------
__global__ void __launch_bounds__(256) gemm_final_kernel(float* __restrict__ out)
{
    const float* glu  = g_arena + OFF_GLU;
    const float* res1 = g_arena + OFF_RES1;
    const int N = CC, K = KP2;

    __shared__ float As[2][ASZ];
    __shared__ float Bs[2][BSZ];

    int bm = blockIdx.y * 128;
    int bn = blockIdx.x * 128;
    int tid = threadIdx.x;
    int lane = tid & 31, warp = tid >> 5;
    int wm0 = (warp >> 1) * 32, wn0 = (warp & 1) * 64;
    int grp = lane >> 2, qd = lane & 3;
    int aRow = tid >> 1, aCol = (tid & 1) * 8;
    int br0 = tid >> 5, bn4 = (tid & 31) * 4;

    int    am   = bm + aRow;
    int    at   = am & 15;
    float2 st   = g_stats[am];
    float  mean = st.x, rstd = st.y;
    const float* gRow  = glu + (size_t)am*FF;
    const float* gPrev = glu + (size_t)(am - 1)*FF;  // only read when at>0
    const float* Bsrc0 = g_wout + (size_t)br0*N + bn + bn4;
    const float* Bsrc1 = g_wout + (size_t)(br0 + 8)*N + bn + bn4;
    uint32_t sBb = s2u(&Bs[0][0]);
    uint32_t dB0 = (uint32_t)((br0*BSTR + bn4)*4);
    uint32_t dB1 = (uint32_t)(((br0 + 8)*BSTR + bn4)*4);

    float ra[8];
    auto ldgA = [&](int kt) {
        int k0 = kt*16;
        #pragma unroll
        for (int j = 0; j < 8; j++) {
            int k = k0 + aCol + j;
            float v = 0.f;
            if (k < FF) {
                float raw;
                if (k < FHALF)   raw = gRow[k];
                else if (at > 0) raw = gPrev[k];
                else             raw = 0.f;
                v = (raw - mean) * rstd;
            }
            ra[j] = v;
        }
    };
    auto stsA = [&](int buf) {
        float* a = As[buf] + aRow*ASTR + aCol;
        #pragma unroll
        for (int j = 0; j < 8; j++) a[j] = f2tff(ra[j]);
    };
    auto ldgB = [&](int buf, int kt) {
        uint32_t b = sBb + buf*(BSZ*4);
        cpa16(b + dB0, Bsrc0 + (size_t)kt*16*N);
        cpa16(b + dB1, Bsrc1 + (size_t)kt*16*N);
    };

    float acc[2][8][4] = {};
    const int nk = K >> 4;
    ldgA(0); ldgB(0, 0); CP_COMMIT;
    stsA(0);
    CP_WAIT0; __syncthreads();
    for (int i = 0; i < nk; i++) {
        int buf = i & 1;
        if (i + 1 < nk) { ldgA(i + 1); ldgB((i + 1) & 1, i + 1); CP_COMMIT; }
        #pragma unroll
        for (int kc = 0; kc < 16; kc += 8) {
            uint32_t af[2][4];
            #pragma unroll
            for (int mi = 0; mi < 2; mi++) {
                int r = wm0 + mi*16 + grp;
                const float* as = As[buf];
                af[mi][0] = __float_as_uint(as[r*ASTR + kc + qd]);
                af[mi][1] = __float_as_uint(as[(r + 8)*ASTR + kc + qd]);
                af[mi][2] = __float_as_uint(as[r*ASTR + kc + qd + 4]);
                af[mi][3] = __float_as_uint(as[(r + 8)*ASTR + kc + qd + 4]);
            }
            uint32_t bf[8][2];
            #pragma unroll
            for (int ni = 0; ni < 8; ni++) {
                int c = wn0 + ni*8 + grp;
                const float* bs = Bs[buf];
                bf[ni][0] = __float_as_uint(bs[(kc + qd)*BSTR + c]);
                bf[ni][1] = __float_as_uint(bs[(kc + qd + 4)*BSTR + c]);
            }
            #pragma unroll
            for (int mi = 0; mi < 2; mi++)
                #pragma unroll
                for (int ni = 0; ni < 8; ni++)
                    mma8(acc[mi][ni], af[mi], bf[ni]);
        }
        if (i + 1 < nk) stsA((i + 1) & 1);
        CP_WAIT0;
        __syncthreads();
    }

    // epilogue: scatter to (b, n, t, h, w) + residual
    #pragma unroll
    for (int mi = 0; mi < 2; mi++) {
        #pragma unroll
        for (int half = 0; half < 2; half++) {
            int m  = bm + wm0 + mi*16 + grp + half*8;
            int sI = m >> 4, t = m & 15;
            int b  = sI >> 10, hw = sI & 1023;
            #pragma unroll
            for (int ni = 0; ni < 8; ni++) {
                int c = bn + wn0 + ni*8 + 2*qd;
                #pragma unroll
                for (int l = 0; l < 2; l++) {
                    int n = c + l;
                    out[((size_t)(b*CC + n)*TT + t)*(HH*WW) + hw] =
                        acc[mi][ni][half*2 + l] + res1[(size_t)m*CC + n];
                }
            }
        }
    }
}

// ---------------- launch ----------------
extern "C" void kernel_launch(void* const* d_in, const int* in_sizes, int n_in,
                              void* d_out, int out_size)
{
    (void)in_sizes; (void)n_in; (void)out_size;
    const float* x     = (const float*)d_in[0];
    const int*   fr    = (const int*)  d_in[1];
    const float* gnorm = (const float*)d_in[2];
    const float* Wq    = (const float*)d_in[3];
    const float* Wkv   = (const float*)d_in[4];
    const float* Wo    = (const float*)d_in[5];
    const float* pos   = (const float*)d_in[6];
    const float* fre   = (const float*)d_in[7];
    const float* w1    = (const float*)d_in[8];
    const float* b1    = (const float*)d_in[9];
    const float* w2    = (const float*)d_in[10];
    const float* b2    = (const float*)d_in[11];
    const float* w3    = (const float*)d_in[12];
    const float* b3    = (const float*)d_in[13];
    const float* Win   = (const float*)d_in[14];
    const float* chang = (const float*)d_in[15];
    const float* Wout  = (const float*)d_in[16];
    float* out = (float*)d_out;

    const int SMEM_GEMM = (3*ASZ + 3*BSZ)*4;          // 56832 B
    const int SMEM_GLU  = (3*ASZ + 6*BSZ2)*4;         // 58368 B
    static int attr_done = 0;
    if (!attr_done) {
        cudaFuncSetAttribute(gemm_async_kernel,
            cudaFuncAttributeMaxDynamicSharedMemorySize, SMEM_GEMM);
        cudaFuncSetAttribute(gemm_glu_kernel,
            cudaFuncAttributeMaxDynamicSharedMemorySize, SMEM_GLU);
        attr_done = 1;
    }

    prep_kernel<<<(PTOT + 255)/256, 256>>>(Wq, Wkv, Wo, Win, chang, Wout);
    bias_kernel<<<256, 256>>>(w1, b1, w2, b2, w3, b3);
    embed_norm_kernel<<<dim3(CC/16, HH, BB), 256>>>(x, fr, gnorm, pos, fre);
    // qkv = xn @ [Wq|Wkv]
    gemm_async_kernel<<<dim3(1536/128, MM/128), 256, SMEM_GEMM>>>(1536, CC, 0, 0, 0, 0);
    attn_kernel<<<SS*HEADS, 128>>>();
    // res1 = o @ Wo + xt
    gemm_async_kernel<<<dim3(CC/128, MM/128), 256, SMEM_GEMM>>>(CC, CC, 1, 1, 1, 1);
    // glu = (res1 @ Win)[:FF] * gelu((res1 @ Win)[FF:])
    gemm_glu_kernel<<<dim3(NWIN/64, MM/128), 256, SMEM_GLU>>>();
    stats_kernel<<<MM, 256>>>();
    gemm_final_kernel<<<dim3(CC/128, MM/128), 256>>>(out);
}